// round 12
// baseline (speedup 1.0000x reference)
#include <cuda_runtime.h>
#include <cstdint>

#define Nn  50000
#define Ee  800000
#define NGg 128
#define Dd  128
#define Mm  2

// ---------------- scratch ----------------
__device__ float g_hA[Mm * Nn * Dd];
__device__ float g_hB[Mm * Nn * Dd];
__device__ float g_Y1[32 * Dd];     // x_table @ Wg1
__device__ float g_Y2[32 * Dd];     // (x_table * (1+at)) @ Wg1
__device__ int   g_deg[Nn];
__device__ int   g_rowptr[Nn + 1];
__device__ int   g_cursor[Nn];
__device__ int   g_col[Ee];
__device__ float g_pred[Nn];
__device__ int   g_counts[NGg];
__device__ unsigned char g_flag[Mm * Nn];
__device__ float g_hg[Mm * NGg * Dd];
__device__ int   g_amark[Mm * Nn];
__device__ int   g_alist[Mm * Nn];
__device__ int   g_naff;

// ---------------- threefry2x32 ----------------
static __host__ __device__ inline unsigned rotl32(unsigned v, int r) {
    return (v << r) | (v >> (32 - r));
}
static __host__ __device__ inline void tf2x32(unsigned k0, unsigned k1,
                                              unsigned& x0, unsigned& x1) {
    unsigned k2 = k0 ^ k1 ^ 0x1BD11BDAu;
    x0 += k0; x1 += k1;
#define TFR(r) { x0 += x1; x1 = rotl32(x1, (r)); x1 ^= x0; }
    TFR(13) TFR(15) TFR(26) TFR(6)
    x0 += k1; x1 += k2 + 1u;
    TFR(17) TFR(29) TFR(16) TFR(24)
    x0 += k2; x1 += k0 + 2u;
    TFR(13) TFR(15) TFR(26) TFR(6)
    x0 += k0; x1 += k1 + 3u;
    TFR(17) TFR(29) TFR(16) TFR(24)
    x0 += k1; x1 += k2 + 4u;
    TFR(13) TFR(15) TFR(26) TFR(6)
    x0 += k2; x1 += k0 + 5u;
#undef TFR
}

static __device__ __forceinline__ uint32_t f2tf32(float f) {
    uint32_t r;
    asm("cvt.rna.tf32.f32 %0, %1;" : "=r"(r) : "f"(f));
    return r;
}

// ---------------- fp32 gather (MLP-unrolled) ----------------
static __device__ __forceinline__ float4 gather_row(const float* __restrict__ base,
                                                    int n, int lane, float4 acc) {
    int beg = g_rowptr[n], end = g_rowptr[n + 1];
    float4 a1 = make_float4(0.f, 0.f, 0.f, 0.f);
    float4 a2 = make_float4(0.f, 0.f, 0.f, 0.f);
    float4 a3 = make_float4(0.f, 0.f, 0.f, 0.f);
    for (int b0 = beg; b0 < end; b0 += 32) {
        int lim = end - b0; if (lim > 32) lim = 32;
        int cidx = (lane < lim) ? g_col[b0 + lane] : 0;
        int j = 0;
        for (; j + 4 <= lim; j += 4) {
            int s0 = __shfl_sync(0xffffffffu, cidx, j);
            int s1 = __shfl_sync(0xffffffffu, cidx, j + 1);
            int s2 = __shfl_sync(0xffffffffu, cidx, j + 2);
            int s3 = __shfl_sync(0xffffffffu, cidx, j + 3);
            float4 v0 = *(const float4*)(base + (size_t)s0 * Dd + lane * 4);
            float4 v1 = *(const float4*)(base + (size_t)s1 * Dd + lane * 4);
            float4 v2 = *(const float4*)(base + (size_t)s2 * Dd + lane * 4);
            float4 v3 = *(const float4*)(base + (size_t)s3 * Dd + lane * 4);
            acc.x += v0.x; acc.y += v0.y; acc.z += v0.z; acc.w += v0.w;
            a1.x += v1.x; a1.y += v1.y; a1.z += v1.z; a1.w += v1.w;
            a2.x += v2.x; a2.y += v2.y; a2.z += v2.z; a2.w += v2.w;
            a3.x += v3.x; a3.y += v3.y; a3.z += v3.z; a3.w += v3.w;
        }
        for (; j < lim; j++) {
            int s0 = __shfl_sync(0xffffffffu, cidx, j);
            float4 v0 = *(const float4*)(base + (size_t)s0 * Dd + lane * 4);
            acc.x += v0.x; acc.y += v0.y; acc.z += v0.z; acc.w += v0.w;
        }
    }
    acc.x += a1.x + a2.x + a3.x;
    acc.y += a1.y + a2.y + a3.y;
    acc.z += a1.z + a2.z + a3.z;
    acc.w += a1.w + a2.w + a3.w;
    return acc;
}

// ---------------- small kernels ----------------
__global__ void k_reset() {
    int i = blockIdx.x * blockDim.x + threadIdx.x;
    if (i < Mm * Nn) { g_flag[i] = 0; g_amark[i] = 0; }
    if (i < Nn) { g_deg[i] = 0; g_cursor[i] = 0; }
    if (i < Mm * NGg * Dd) g_hg[i] = 0.f;
    if (i < NGg) g_counts[i] = 0;
    if (i == 0) g_naff = 0;
}

__global__ void k_hist(const int* __restrict__ edst, const int* __restrict__ batch) {
    int e = blockIdx.x * blockDim.x + threadIdx.x;
    if (e < Ee) atomicAdd(&g_deg[edst[e]], 1);
    if (e < Nn) atomicAdd(&g_counts[batch[e]], 1);
}

__global__ void k_scan() {
    __shared__ int ss[1024];
    int tid = threadIdx.x;
    const int CH = (Nn + 1023) / 1024;
    int beg = tid * CH;
    int end = beg + CH; if (end > Nn) end = Nn;
    int s = 0;
    for (int i = beg; i < end; i++) s += g_deg[i];
    ss[tid] = s;
    __syncthreads();
    for (int off = 1; off < 1024; off <<= 1) {
        int v = (tid >= off) ? ss[tid - off] : 0;
        __syncthreads();
        ss[tid] += v;
        __syncthreads();
    }
    int base = (tid == 0) ? 0 : ss[tid - 1];
    for (int i = beg; i < end; i++) { g_rowptr[i] = base; base += g_deg[i]; }
    if (tid == 1023) g_rowptr[Nn] = ss[1023];
}

__global__ void k_fill(const int* __restrict__ esrc, const int* __restrict__ edst) {
    int e = blockIdx.x * blockDim.x + threadIdx.x;
    if (e >= Ee) return;
    int d = edst[e];
    int p = atomicAdd(&g_cursor[d], 1);
    g_col[g_rowptr[d] + p] = esrc[e];
}

// ---------------- Y tables: Y1 = xt@W1, Y2 = (xt*(1+at))@W1 ----------------
__global__ __launch_bounds__(512) void k_prep(const float* __restrict__ x_table,
                                              const float* __restrict__ anchor_table,
                                              const float* __restrict__ Wg) {
    __shared__ float sXT[32 * Dd];
    __shared__ float sAT[Dd];
    int t = threadIdx.x;
    for (int i = t; i < 32 * Dd; i += 512) sXT[i] = x_table[i];
    if (t < Dd) sAT[t] = anchor_table[Dd + t];   // row 1
    __syncthreads();
    int c = t & 127, vg = t >> 7;  // vg in 0..3; each handles v = vg, vg+4, ... vg+28
    float y1[8], y2[8];
#pragma unroll
    for (int i = 0; i < 8; i++) { y1[i] = 0.f; y2[i] = 0.f; }
    for (int k = 0; k < Dd; k++) {
        float w = Wg[k * Dd + c];
        float wa = w * (1.f + sAT[k]);
#pragma unroll
        for (int i = 0; i < 8; i++) {
            float x = sXT[(vg + i * 4) * Dd + k];
            y1[i] = fmaf(x, w, y1[i]);
            y2[i] = fmaf(x, wa, y2[i]);
        }
    }
#pragma unroll
    for (int i = 0; i < 8; i++) {
        g_Y1[(vg + i * 4) * Dd + c] = y1[i];
        g_Y2[(vg + i * 4) * Dd + c] = y2[i];
    }
}

// ---------------- pass-1 L1: h1[n] = relu(Y1[xi n] + sum Y1[xi s] + bg) ----------------
__global__ __launch_bounds__(256) void k_gather1(const int* __restrict__ x_idx,
                                                 const float* __restrict__ bg) {
    __shared__ float sY[32 * Dd];
    int t = threadIdx.x, lane = t & 31;
    for (int i = t; i < 32 * Dd; i += 256) sY[i] = g_Y1[i];
    __syncthreads();
    float4 bias = *(const float4*)(bg + lane * 4);
    int w = (blockIdx.x * 256 + t) >> 5;
    int nw = (gridDim.x * 256) >> 5;
    for (int n = w; n < Nn; n += nw) {
        int xi = x_idx[n];
        float4 acc = *(const float4*)(sY + xi * Dd + lane * 4);
        float4 a1 = make_float4(0.f, 0.f, 0.f, 0.f);
        float4 a2 = make_float4(0.f, 0.f, 0.f, 0.f);
        float4 a3 = make_float4(0.f, 0.f, 0.f, 0.f);
        int beg = g_rowptr[n], end = g_rowptr[n + 1];
        for (int b0 = beg; b0 < end; b0 += 32) {
            int lim = end - b0; if (lim > 32) lim = 32;
            int xv = (lane < lim) ? x_idx[g_col[b0 + lane]] : 0;
            int j = 0;
            for (; j + 4 <= lim; j += 4) {
                int s0 = __shfl_sync(0xffffffffu, xv, j);
                int s1 = __shfl_sync(0xffffffffu, xv, j + 1);
                int s2 = __shfl_sync(0xffffffffu, xv, j + 2);
                int s3 = __shfl_sync(0xffffffffu, xv, j + 3);
                float4 v0 = *(const float4*)(sY + s0 * Dd + lane * 4);
                float4 v1 = *(const float4*)(sY + s1 * Dd + lane * 4);
                float4 v2 = *(const float4*)(sY + s2 * Dd + lane * 4);
                float4 v3 = *(const float4*)(sY + s3 * Dd + lane * 4);
                acc.x += v0.x; acc.y += v0.y; acc.z += v0.z; acc.w += v0.w;
                a1.x += v1.x; a1.y += v1.y; a1.z += v1.z; a1.w += v1.w;
                a2.x += v2.x; a2.y += v2.y; a2.z += v2.z; a2.w += v2.w;
                a3.x += v3.x; a3.y += v3.y; a3.z += v3.z; a3.w += v3.w;
            }
            for (; j < lim; j++) {
                int s0 = __shfl_sync(0xffffffffu, xv, j);
                float4 v0 = *(const float4*)(sY + s0 * Dd + lane * 4);
                acc.x += v0.x; acc.y += v0.y; acc.z += v0.z; acc.w += v0.w;
            }
        }
        acc.x = fmaxf(acc.x + a1.x + a2.x + a3.x + bias.x, 0.f);
        acc.y = fmaxf(acc.y + a1.y + a2.y + a3.y + bias.y, 0.f);
        acc.z = fmaxf(acc.z + a1.z + a2.z + a3.z + bias.z, 0.f);
        acc.w = fmaxf(acc.w + a1.w + a2.w + a3.w + bias.w, 0.f);
        *(float4*)(g_hA + (size_t)n * Dd + lane * 4) = acc;
        *(float4*)(g_hA + (size_t)(n + Nn) * Dd + lane * 4) = acc;
    }
}

// ---------------- sparse patch: vocab-based, Y1/Y2 select by flag ----------------
__global__ __launch_bounds__(256) void k_patch(const int* __restrict__ x_idx,
                                               const float* __restrict__ bg) {
    __shared__ float sY[2 * 32 * Dd];   // [0]=Y1, [4096]=Y2
    int t = threadIdx.x, lane = t & 31;
    for (int i = t; i < 32 * Dd; i += 256) { sY[i] = g_Y1[i]; sY[4096 + i] = g_Y2[i]; }
    __syncthreads();
    float4 bias = *(const float4*)(bg + lane * 4);
    int w = (blockIdx.x * 256 + t) >> 5;
    int nw = (gridDim.x * 256) >> 5;
    int total = g_naff;
    for (int i = w; i < total; i += nw) {
        int row = g_alist[i];
        int m = row / Nn, n = row - m * Nn;
        int selfo = g_flag[row] ? 4096 : 0;
        float4 acc = *(const float4*)(sY + selfo + x_idx[n] * Dd + lane * 4);
        int beg = g_rowptr[n], end = g_rowptr[n + 1];
        for (int b0 = beg; b0 < end; b0 += 32) {
            int lim = end - b0; if (lim > 32) lim = 32;
            int pk = 0;
            if (lane < lim) {
                int s = g_col[b0 + lane];
                pk = x_idx[s] | ((int)g_flag[m * Nn + s] << 12);
            }
            for (int j = 0; j < lim; j++) {
                int p = __shfl_sync(0xffffffffu, pk, j);
                const float4 v = *(const float4*)(sY + (p & 0xFFF) * Dd + (p >> 12) * 4096 + lane * 4);
                acc.x += v.x; acc.y += v.y; acc.z += v.z; acc.w += v.w;
            }
        }
        acc.x = fmaxf(acc.x + bias.x, 0.f);
        acc.y = fmaxf(acc.y + bias.y, 0.f);
        acc.z = fmaxf(acc.z + bias.z, 0.f);
        acc.w = fmaxf(acc.w + bias.w, 0.f);
        *(float4*)(g_hA + (size_t)row * Dd + lane * 4) = acc;
    }
}

// ---------------- pass-1 L2: fp32 gather+GEMM + pred epilogue ----------------
__global__ __launch_bounds__(256) void k_pred2(
    const float* __restrict__ W, const float* __restrict__ bias,
    const float* __restrict__ Wd, const float* __restrict__ bd)
{
    __shared__ float sIn[64 * 129];
    __shared__ float sW[16 * 128];
    __shared__ int sRow[64];
    int t = threadIdx.x, lane = t & 31, wid = t >> 5;
    int rg = t >> 4, cg = t & 15;

    for (int tile = blockIdx.x; tile * 64 < Nn; tile += gridDim.x) {
        if (t < 64) {
            int idx = tile * 64 + t;
            sRow[t] = (idx < Nn) ? idx : -1;
        }
        __syncthreads();

        for (int rr = wid; rr < 64; rr += 8) {
            int grow = sRow[rr];
            float4 acc = make_float4(0.f, 0.f, 0.f, 0.f);
            if (grow >= 0) {
                acc = *(const float4*)(g_hA + (size_t)grow * Dd + lane * 4);
                acc = gather_row(g_hA, grow, lane, acc);
            }
            float* d = &sIn[rr * 129 + lane * 4];
            d[0] = acc.x; d[1] = acc.y; d[2] = acc.z; d[3] = acc.w;
        }
        __syncthreads();

        float acc[4][8];
#pragma unroll
        for (int r = 0; r < 4; r++)
#pragma unroll
            for (int j = 0; j < 8; j++) acc[r][j] = 0.f;

        for (int kc = 0; kc < 8; kc++) {
            const float4* Ws = (const float4*)(W + kc * 16 * 128);
            ((float4*)sW)[t] = Ws[t];
            ((float4*)sW)[t + 256] = Ws[t + 256];
            __syncthreads();
#pragma unroll
            for (int kk = 0; kk < 16; kk++) {
                float a[4], w[8];
#pragma unroll
                for (int r = 0; r < 4; r++) a[r] = sIn[(rg + 16 * r) * 129 + kc * 16 + kk];
#pragma unroll
                for (int j = 0; j < 8; j++) w[j] = sW[kk * 128 + cg + 16 * j];
#pragma unroll
                for (int r = 0; r < 4; r++)
#pragma unroll
                    for (int j = 0; j < 8; j++) acc[r][j] = fmaf(a[r], w[j], acc[r][j]);
            }
            __syncthreads();
        }

#pragma unroll
        for (int r = 0; r < 4; r++) {
            int grow = sRow[rg + 16 * r];
            float p = 0.f;
#pragma unroll
            for (int j = 0; j < 8; j++) {
                float v = fmaxf(acc[r][j] + bias[cg + 16 * j], 0.f);
                p = fmaf(v, Wd[cg + 16 * j], p);
            }
#pragma unroll
            for (int o = 8; o > 0; o >>= 1) p += __shfl_xor_sync(0xffffffffu, p, o);
            if (cg == 0 && grow >= 0) g_pred[grow] = p + bd[0];
        }
        __syncthreads();
    }
}

// ---------------- tf32 mma.sync GEMM (R9 config: fp32 in/out) ----------------
#define SW_STR 136
#define SI_STR 132
#define SMEM_MMA ((128 * SW_STR + 64 * SI_STR) * 4 + 64 * 4)

static __device__ __forceinline__ void mma_tf32(float* c, const uint32_t* a, const uint32_t* b) {
    asm volatile(
        "mma.sync.aligned.m16n8k8.row.col.f32.tf32.tf32.f32 "
        "{%0,%1,%2,%3}, {%4,%5,%6,%7}, {%8,%9}, {%0,%1,%2,%3};"
        : "+f"(c[0]), "+f"(c[1]), "+f"(c[2]), "+f"(c[3])
        : "r"(a[0]), "r"(a[1]), "r"(a[2]), "r"(a[3]), "r"(b[0]), "r"(b[1]));
}

__global__ __launch_bounds__(256) void k_mma(
    int gather, int pool, int insel,
    const float* __restrict__ W, const float* __restrict__ bias,
    const int* __restrict__ batch, int nrows)
{
    extern __shared__ float sm[];
    float* sW = sm;
    float* sIn = sm + 128 * SW_STR;
    int* sRow = (int*)(sIn + 64 * SI_STR);
    const float* in = (insel == 2) ? g_hA : g_hB;
    int t = threadIdx.x, lane = t & 31, wid = t >> 5;
    int gid = lane >> 2, tig = lane & 3;
    int wr = wid >> 2, wc = wid & 3;

    for (int idx = t; idx < 16384; idx += 256) {
        int k = idx >> 7, c = idx & 127;
        sW[k * SW_STR + c] = __uint_as_float(f2tf32(W[idx]));
    }

    int ntile = (nrows + 63) >> 6;
    for (int tile = blockIdx.x; tile < ntile; tile += gridDim.x) {
        if (t < 64) {
            int idx = tile * 64 + t;
            sRow[t] = (idx < nrows) ? idx : -1;
        }
        __syncthreads();

        for (int rr = wid; rr < 64; rr += 8) {
            int grow = sRow[rr];
            float4 acc = make_float4(0.f, 0.f, 0.f, 0.f);
            if (grow >= 0) {
                int m = grow / Nn, n = grow - m * Nn;
                const float* base = in + (size_t)m * Nn * Dd;
                acc = *(const float4*)(base + (size_t)n * Dd + lane * 4);
                if (gather) acc = gather_row(base, n, lane, acc);
            }
            float* d = &sIn[rr * SI_STR + lane * 4];
            d[0] = __uint_as_float(f2tf32(acc.x));
            d[1] = __uint_as_float(f2tf32(acc.y));
            d[2] = __uint_as_float(f2tf32(acc.z));
            d[3] = __uint_as_float(f2tf32(acc.w));
        }
        __syncthreads();

        float c_[2][4][4];
#pragma unroll
        for (int mt = 0; mt < 2; mt++)
#pragma unroll
            for (int nt = 0; nt < 4; nt++)
#pragma unroll
                for (int q = 0; q < 4; q++) c_[mt][nt][q] = 0.f;

#pragma unroll 4
        for (int ks = 0; ks < 16; ks++) {
            int k0 = ks * 8;
            uint32_t a[2][4], b[4][2];
#pragma unroll
            for (int mt = 0; mt < 2; mt++) {
                const float* Ap = sIn + (wr * 32 + mt * 16 + gid) * SI_STR + k0 + tig;
                a[mt][0] = __float_as_uint(Ap[0]);
                a[mt][1] = __float_as_uint(Ap[8 * SI_STR]);
                a[mt][2] = __float_as_uint(Ap[4]);
                a[mt][3] = __float_as_uint(Ap[8 * SI_STR + 4]);
            }
#pragma unroll
            for (int nt = 0; nt < 4; nt++) {
                const float* Bp = sW + (k0 + tig) * SW_STR + wc * 32 + nt * 8 + gid;
                b[nt][0] = __float_as_uint(Bp[0]);
                b[nt][1] = __float_as_uint(Bp[4 * SW_STR]);
            }
#pragma unroll
            for (int mt = 0; mt < 2; mt++)
#pragma unroll
                for (int nt = 0; nt < 4; nt++)
                    mma_tf32(c_[mt][nt], a[mt], b[nt]);
        }
        __syncthreads();

#pragma unroll
        for (int mt = 0; mt < 2; mt++) {
#pragma unroll
            for (int nt = 0; nt < 4; nt++) {
                int col = wc * 32 + nt * 8 + tig * 2;
                int row = wr * 32 + mt * 16 + gid;
                float b0 = bias[col], b1 = bias[col + 1];
                sIn[row * SI_STR + col]           = fmaxf(c_[mt][nt][0] + b0, 0.f);
                sIn[row * SI_STR + col + 1]       = fmaxf(c_[mt][nt][1] + b1, 0.f);
                sIn[(row + 8) * SI_STR + col]     = fmaxf(c_[mt][nt][2] + b0, 0.f);
                sIn[(row + 8) * SI_STR + col + 1] = fmaxf(c_[mt][nt][3] + b1, 0.f);
            }
        }
        __syncthreads();

        if (pool) {
            int col = t & 127, half = t >> 7;
            float s = 0.f; int cur = -1;
            for (int rr = half * 32; rr < half * 32 + 32; rr++) {
                int grow = sRow[rr]; if (grow < 0) continue;
                int m = grow / Nn;
                int key = m * NGg + batch[grow - m * Nn];
                if (key != cur) {
                    if (cur >= 0) atomicAdd(&g_hg[(size_t)cur * Dd + col], s);
                    cur = key; s = 0.f;
                }
                s += sIn[rr * SI_STR + col];
            }
            if (cur >= 0) atomicAdd(&g_hg[(size_t)cur * Dd + col], s);
        } else {
            for (int idx = t; idx < 2048; idx += 256) {
                int rr = idx >> 5, q = idx & 31;
                int grow = sRow[rr];
                if (grow < 0) continue;
                *(float4*)(g_hB + (size_t)grow * Dd + q * 4) =
                    *(float4*)(sIn + rr * SI_STR + q * 4);
            }
        }
        __syncthreads();
    }
}

// ---------------- fused per-graph sampling ----------------
static __device__ __forceinline__ float score_fn(int n, int m, float mx, float ssum,
                                                 unsigned fk0, unsigned fk1) {
    float e = expf(g_pred[n] - mx);
    float p = e / ssum;
    float lp = logf(p + 1e-15f);
    unsigned x0 = 0u, x1 = (unsigned)(m * Nn + n);
    tf2x32(fk0, fk1, x0, x1);
    float u = __uint_as_float((x1 >> 9) | 0x3F800000u) - 1.0f;
    u = fmaxf(u, 0.0f);
    float gum = -logf(-logf(u + 1e-12f) + 1e-12f);
    return lp + gum;
}

__global__ void k_sample(const int* __restrict__ batch, unsigned fk0, unsigned fk1) {
    __shared__ float fb[8];
    __shared__ int ib[8];
    __shared__ int sSE[2];
    __shared__ float sMx, sSum, sBest;
    int g = blockIdx.x, t = threadIdx.x, lane = t & 31, wid = t >> 5;
    if (t < 2) {
        int tgt = g + t;
        int lo = 0, hi = Nn;
        while (lo < hi) { int mid = (lo + hi) >> 1; if (batch[mid] < tgt) lo = mid + 1; else hi = mid; }
        sSE[t] = lo;
    }
    __syncthreads();
    int s0 = sSE[0], s1 = sSE[1];

    float mx = -3.4e38f;
    for (int n = s0 + t; n < s1; n += 256) mx = fmaxf(mx, g_pred[n]);
#pragma unroll
    for (int o = 16; o > 0; o >>= 1) mx = fmaxf(mx, __shfl_xor_sync(0xffffffffu, mx, o));
    if (lane == 0) fb[wid] = mx;
    __syncthreads();
    if (t == 0) { float x = fb[0]; for (int i = 1; i < 8; i++) x = fmaxf(x, fb[i]); sMx = x; }
    __syncthreads();
    float gmx = sMx;

    float sm = 0.f;
    for (int n = s0 + t; n < s1; n += 256) sm += expf(g_pred[n] - gmx);
#pragma unroll
    for (int o = 16; o > 0; o >>= 1) sm += __shfl_xor_sync(0xffffffffu, sm, o);
    if (lane == 0) fb[wid] = sm;
    __syncthreads();
    if (t == 0) { float x = 0.f; for (int i = 0; i < 8; i++) x += fb[i]; sSum = x; }
    __syncthreads();
    float gsum = sSum;

    for (int m = 0; m < Mm; m++) {
        float best = -3.4e38f;
        for (int n = s0 + t; n < s1; n += 256)
            best = fmaxf(best, score_fn(n, m, gmx, gsum, fk0, fk1));
#pragma unroll
        for (int o = 16; o > 0; o >>= 1) best = fmaxf(best, __shfl_xor_sync(0xffffffffu, best, o));
        if (lane == 0) fb[wid] = best;
        __syncthreads();
        if (t == 0) { float x = fb[0]; for (int i = 1; i < 8; i++) x = fmaxf(x, fb[i]); sBest = x; }
        __syncthreads();
        float gb = sBest;
        __syncthreads();

        int cand = Nn;
        for (int n = s0 + t; n < s1; n += 256)
            if (score_fn(n, m, gmx, gsum, fk0, fk1) >= gb) cand = min(cand, n);
#pragma unroll
        for (int o = 16; o > 0; o >>= 1) cand = min(cand, __shfl_xor_sync(0xffffffffu, cand, o));
        if (lane == 0) ib[wid] = cand;
        __syncthreads();
        if (t == 0) {
            int x = ib[0]; for (int i = 1; i < 8; i++) x = min(x, ib[i]);
            if (x < Nn) {
                g_flag[m * Nn + x] = 1;
                if (atomicExch(&g_amark[m * Nn + x], 1) == 0) {
                    int p = atomicAdd(&g_naff, 1);
                    g_alist[p] = m * Nn + x;
                }
            }
        }
        __syncthreads();
    }
}

// single-pass mark: rows whose L1 aggregation changes per m
__global__ void k_mark(const int* __restrict__ esrc, const int* __restrict__ edst) {
    int e = blockIdx.x * blockDim.x + threadIdx.x;
    if (e >= Ee) return;
    int s = esrc[e];
    unsigned char f0 = g_flag[s];
    unsigned char f1 = g_flag[Nn + s];
    if (!(f0 | f1)) return;
    int d = edst[e];
    if (f0 && atomicExch(&g_amark[d], 1) == 0) {
        int p = atomicAdd(&g_naff, 1);
        g_alist[p] = d;
    }
    if (f1 && atomicExch(&g_amark[Nn + d], 1) == 0) {
        int p = atomicAdd(&g_naff, 1);
        g_alist[p] = Nn + d;
    }
}

__global__ void k_final(const float* __restrict__ Wp, const float* __restrict__ bp,
                        float* __restrict__ out) {
    __shared__ float red[128];
    int g = blockIdx.x, t = threadIdx.x;
    int c = g_counts[g]; if (c < 1) c = 1;
    float inv = 1.0f / (float)c;
    float hsum = (g_hg[(size_t)g * Dd + t] + g_hg[((size_t)NGg + g) * Dd + t]) * inv;
    for (int tt = 0; tt < 10; tt++) {
        red[t] = hsum * Wp[t * 10 + tt];
        __syncthreads();
        for (int off = 64; off > 0; off >>= 1) {
            if (t < off) red[t] += red[t + off];
            __syncthreads();
        }
        if (t == 0) out[g * 10 + tt] = red[0] * 0.5f + bp[tt];
        __syncthreads();
    }
}

// ---------------- launch ----------------
static inline int cdiv(int a, int b) { return (a + b - 1) / b; }

extern "C" void kernel_launch(void* const* d_in, const int* in_sizes, int n_in,
                              void* d_out, int out_size) {
    const int*   x_idx        = (const int*)d_in[0];
    const int*   esrc         = (const int*)d_in[1];
    const int*   edst         = (const int*)d_in[2];
    const int*   batch        = (const int*)d_in[3];
    const float* x_table      = (const float*)d_in[4];
    const float* anchor_table = (const float*)d_in[5];
    const float* Wg           = (const float*)d_in[6];
    const float* bg           = (const float*)d_in[7];
    const float* Wn           = (const float*)d_in[8];
    const float* bn           = (const float*)d_in[9];
    const float* Wd           = (const float*)d_in[10];
    const float* bd           = (const float*)d_in[11];
    const float* Wp           = (const float*)d_in[12];
    const float* bp           = (const float*)d_in[13];
    float* out = (float*)d_out;

    unsigned fk0 = 0u, fk1 = 1u;
    tf2x32(0u, 1u, fk0, fk1);

    cudaFuncSetAttribute(k_mma, cudaFuncAttributeMaxDynamicSharedMemorySize, SMEM_MMA);

    // setup + Y tables
    k_reset<<<cdiv(Mm * Nn, 256), 256>>>();
    k_hist<<<cdiv(Ee, 256), 256>>>(edst, batch);
    k_scan<<<1, 1024>>>();
    k_fill<<<cdiv(Ee, 256), 256>>>(esrc, edst);
    k_prep<<<1, 512>>>(x_table, anchor_table, Wg);

    // pass1 L1: vocab-gather of Y1 (GEMM-free), dual-write fp32 hA
    k_gather1<<<782, 256>>>(x_idx, bg);
    // pass1 L2: fp32 gather+GEMM + pred epilogue
    k_pred2<<<782, 256>>>(Wg + Dd * Dd, bg + Dd, Wd, bd);

    // anchor sampling + single-pass affected-row marking
    k_sample<<<NGg, 256>>>(batch, fk0, fk1);
    k_mark<<<cdiv(Ee, 256), 256>>>(esrc, edst);

    // pass2 L1: sparse patch via Y1/Y2 vocab gather (GEMM-free)
    k_patch<<<148, 256>>>(x_idx, bg);

    // pass2 L2 (tf32 mma): hA -> hB
    k_mma<<<296, 256, SMEM_MMA>>>(1, 0, 2, Wg + Dd * Dd, bg + Dd, batch, Mm * Nn);
    // node MLP + pooled epilogue (tf32): hB -> hg
    k_mma<<<296, 256, SMEM_MMA>>>(0, 1, 3, Wn, bn, batch, Mm * Nn);

    // final projection + mean over m
    k_final<<<NGg, 128>>>(Wp, bp, out);
}

// round 15
// speedup vs baseline: 1.4734x; 1.4734x over previous
#include <cuda_runtime.h>
#include <cstdint>

#define Nn  50000
#define Ee  800000
#define NGg 128
#define Dd  128
#define Mm  2

// ---------------- scratch ----------------
__device__ float g_hA[Mm * Nn * Dd];
__device__ float g_hB[Mm * Nn * Dd];
__device__ float g_Y1[32 * Dd];     // x_table @ Wg1 (precomputed)
__device__ int   g_deg[Nn];
__device__ int   g_rowptr[Nn + 1];
__device__ int   g_cursor[Nn];
__device__ int   g_col[Ee];
__device__ float g_pred[Nn];
__device__ int   g_counts[NGg];
__device__ unsigned char g_flag[Mm * Nn];
__device__ float g_hg[Mm * NGg * Dd];
__device__ int   g_amark[Mm * Nn];
__device__ int   g_alist[Mm * Nn];
__device__ int   g_naff;

// ---------------- threefry2x32 ----------------
static __host__ __device__ inline unsigned rotl32(unsigned v, int r) {
    return (v << r) | (v >> (32 - r));
}
static __host__ __device__ inline void tf2x32(unsigned k0, unsigned k1,
                                              unsigned& x0, unsigned& x1) {
    unsigned k2 = k0 ^ k1 ^ 0x1BD11BDAu;
    x0 += k0; x1 += k1;
#define TFR(r) { x0 += x1; x1 = rotl32(x1, (r)); x1 ^= x0; }
    TFR(13) TFR(15) TFR(26) TFR(6)
    x0 += k1; x1 += k2 + 1u;
    TFR(17) TFR(29) TFR(16) TFR(24)
    x0 += k2; x1 += k0 + 2u;
    TFR(13) TFR(15) TFR(26) TFR(6)
    x0 += k0; x1 += k1 + 3u;
    TFR(17) TFR(29) TFR(16) TFR(24)
    x0 += k1; x1 += k2 + 4u;
    TFR(13) TFR(15) TFR(26) TFR(6)
    x0 += k2; x1 += k0 + 5u;
#undef TFR
}

static __device__ __forceinline__ uint32_t f2tf32(float f) {
    uint32_t r;
    asm("cvt.rna.tf32.f32 %0, %1;" : "=r"(r) : "f"(f));
    return r;
}

// ---------------- fp32 gather (MLP-unrolled) ----------------
static __device__ __forceinline__ float4 gather_row(const float* __restrict__ base,
                                                    int n, int lane, float4 acc) {
    int beg = g_rowptr[n], end = g_rowptr[n + 1];
    float4 a1 = make_float4(0.f, 0.f, 0.f, 0.f);
    float4 a2 = make_float4(0.f, 0.f, 0.f, 0.f);
    float4 a3 = make_float4(0.f, 0.f, 0.f, 0.f);
    for (int b0 = beg; b0 < end; b0 += 32) {
        int lim = end - b0; if (lim > 32) lim = 32;
        int cidx = (lane < lim) ? g_col[b0 + lane] : 0;
        int j = 0;
        for (; j + 4 <= lim; j += 4) {
            int s0 = __shfl_sync(0xffffffffu, cidx, j);
            int s1 = __shfl_sync(0xffffffffu, cidx, j + 1);
            int s2 = __shfl_sync(0xffffffffu, cidx, j + 2);
            int s3 = __shfl_sync(0xffffffffu, cidx, j + 3);
            float4 v0 = *(const float4*)(base + (size_t)s0 * Dd + lane * 4);
            float4 v1 = *(const float4*)(base + (size_t)s1 * Dd + lane * 4);
            float4 v2 = *(const float4*)(base + (size_t)s2 * Dd + lane * 4);
            float4 v3 = *(const float4*)(base + (size_t)s3 * Dd + lane * 4);
            acc.x += v0.x; acc.y += v0.y; acc.z += v0.z; acc.w += v0.w;
            a1.x += v1.x; a1.y += v1.y; a1.z += v1.z; a1.w += v1.w;
            a2.x += v2.x; a2.y += v2.y; a2.z += v2.z; a2.w += v2.w;
            a3.x += v3.x; a3.y += v3.y; a3.z += v3.z; a3.w += v3.w;
        }
        for (; j < lim; j++) {
            int s0 = __shfl_sync(0xffffffffu, cidx, j);
            float4 v0 = *(const float4*)(base + (size_t)s0 * Dd + lane * 4);
            acc.x += v0.x; acc.y += v0.y; acc.z += v0.z; acc.w += v0.w;
        }
    }
    acc.x += a1.x + a2.x + a3.x;
    acc.y += a1.y + a2.y + a3.y;
    acc.z += a1.z + a2.z + a3.z;
    acc.w += a1.w + a2.w + a3.w;
    return acc;
}

// gather from smem vocab-indexed table: per edge only a 4B x_idx load from global
static __device__ __forceinline__ float4 gather_tx(const float* __restrict__ sXT,
                                                   const int* __restrict__ x_idx,
                                                   int n, int lane, float4 acc) {
    int beg = g_rowptr[n], end = g_rowptr[n + 1];
    float4 a1 = make_float4(0.f, 0.f, 0.f, 0.f);
    float4 a2 = make_float4(0.f, 0.f, 0.f, 0.f);
    float4 a3 = make_float4(0.f, 0.f, 0.f, 0.f);
    for (int b0 = beg; b0 < end; b0 += 32) {
        int lim = end - b0; if (lim > 32) lim = 32;
        int xv = 0;
        if (lane < lim) xv = x_idx[g_col[b0 + lane]];
        int j = 0;
        for (; j + 4 <= lim; j += 4) {
            int s0 = __shfl_sync(0xffffffffu, xv, j);
            int s1 = __shfl_sync(0xffffffffu, xv, j + 1);
            int s2 = __shfl_sync(0xffffffffu, xv, j + 2);
            int s3 = __shfl_sync(0xffffffffu, xv, j + 3);
            float4 v0 = *(const float4*)(sXT + s0 * Dd + lane * 4);
            float4 v1 = *(const float4*)(sXT + s1 * Dd + lane * 4);
            float4 v2 = *(const float4*)(sXT + s2 * Dd + lane * 4);
            float4 v3 = *(const float4*)(sXT + s3 * Dd + lane * 4);
            acc.x += v0.x; acc.y += v0.y; acc.z += v0.z; acc.w += v0.w;
            a1.x += v1.x; a1.y += v1.y; a1.z += v1.z; a1.w += v1.w;
            a2.x += v2.x; a2.y += v2.y; a2.z += v2.z; a2.w += v2.w;
            a3.x += v3.x; a3.y += v3.y; a3.z += v3.z; a3.w += v3.w;
        }
        for (; j < lim; j++) {
            int s0 = __shfl_sync(0xffffffffu, xv, j);
            float4 v0 = *(const float4*)(sXT + s0 * Dd + lane * 4);
            acc.x += v0.x; acc.y += v0.y; acc.z += v0.z; acc.w += v0.w;
        }
    }
    acc.x += a1.x + a2.x + a3.x;
    acc.y += a1.y + a2.y + a3.y;
    acc.z += a1.z + a2.z + a3.z;
    acc.w += a1.w + a2.w + a3.w;
    return acc;
}

// virtual x' gather: smem vocab row + flag-predicated anchor scaling (sparse patch)
static __device__ __forceinline__ float4 gather_xm(const float* __restrict__ sXT,
                                                   const int* __restrict__ x_idx,
                                                   int n, int lane, float4 acc,
                                                   float4 av, int m) {
    int beg = g_rowptr[n], end = g_rowptr[n + 1];
    for (int b0 = beg; b0 < end; b0 += 32) {
        int lim = end - b0; if (lim > 32) lim = 32;
        int pk = 0;
        if (lane < lim) {
            int s = g_col[b0 + lane];
            pk = x_idx[s] | ((int)g_flag[m * Nn + s] << 8);
        }
        for (int j = 0; j < lim; j++) {
            int p = __shfl_sync(0xffffffffu, pk, j);
            float4 v = *(const float4*)(sXT + (p & 255) * Dd + lane * 4);
            if (p >> 8) {
                v.x = fmaf(v.x, av.x, v.x);
                v.y = fmaf(v.y, av.y, v.y);
                v.z = fmaf(v.z, av.z, v.z);
                v.w = fmaf(v.w, av.w, v.w);
            }
            acc.x += v.x; acc.y += v.y; acc.z += v.z; acc.w += v.w;
        }
    }
    return acc;
}

// ---------------- small kernels ----------------
__global__ void k_reset() {
    int i = blockIdx.x * blockDim.x + threadIdx.x;
    if (i < Mm * Nn) { g_flag[i] = 0; g_amark[i] = 0; }
    if (i < Nn) { g_deg[i] = 0; g_cursor[i] = 0; }
    if (i < Mm * NGg * Dd) g_hg[i] = 0.f;
    if (i < NGg) g_counts[i] = 0;
    if (i == 0) g_naff = 0;
}

// hist + per-graph node counts (fused)
__global__ void k_hist(const int* __restrict__ edst, const int* __restrict__ batch) {
    int e = blockIdx.x * blockDim.x + threadIdx.x;
    if (e < Ee) atomicAdd(&g_deg[edst[e]], 1);
    if (e < Nn) atomicAdd(&g_counts[batch[e]], 1);
}

// Y1[v] = x_table[v] @ Wg1  (one block per vocab row)
__global__ __launch_bounds__(128) void k_prep(const float* __restrict__ x_table,
                                              const float* __restrict__ Wg) {
    __shared__ float sx[Dd];
    int v = blockIdx.x, c = threadIdx.x;
    sx[c] = x_table[v * Dd + c];
    __syncthreads();
    float y = 0.f;
#pragma unroll 8
    for (int k = 0; k < Dd; k++) y = fmaf(sx[k], Wg[k * Dd + c], y);
    g_Y1[v * Dd + c] = y;
}

__global__ void k_scan() {
    __shared__ int ss[1024];
    int tid = threadIdx.x;
    const int CH = (Nn + 1023) / 1024;
    int beg = tid * CH;
    int end = beg + CH; if (end > Nn) end = Nn;
    int s = 0;
    for (int i = beg; i < end; i++) s += g_deg[i];
    ss[tid] = s;
    __syncthreads();
    for (int off = 1; off < 1024; off <<= 1) {
        int v = (tid >= off) ? ss[tid - off] : 0;
        __syncthreads();
        ss[tid] += v;
        __syncthreads();
    }
    int base = (tid == 0) ? 0 : ss[tid - 1];
    for (int i = beg; i < end; i++) { g_rowptr[i] = base; base += g_deg[i]; }
    if (tid == 1023) g_rowptr[Nn] = ss[1023];
}

__global__ void k_fill(const int* __restrict__ esrc, const int* __restrict__ edst) {
    int e = blockIdx.x * blockDim.x + threadIdx.x;
    if (e >= Ee) return;
    int d = edst[e];
    int p = atomicAdd(&g_cursor[d], 1);
    g_col[g_rowptr[d] + p] = esrc[e];
}

// ---------------- fp32 fused gather(+GEMM) ----------------
// insel: 0 = Y1 from smem table (pass1 L1, NO GEMM — writes relu(sum+bg) dual)
//        1 = virtual x' from smem vocab table (sparse patch, with GEMM)
//        2 = g_hA (pass1 L2, with GEMM)
// mode : 0 = L1 direct write (dual slices)   1 = pred epilogue   2 = patch write
#define SM_FUSED_XT ((64 * 129 + 64 + 32 * 128) * 4)
#define SM_FUSED_H  ((64 * 129 + 64 + 16 * 128) * 4)
__global__ __launch_bounds__(256) void k_fused(
    int insel, int mode,
    const float* __restrict__ W, const float* __restrict__ bias,
    const float* __restrict__ Wd, const float* __restrict__ bd,
    const float* __restrict__ anchor_table,
    const int* __restrict__ x_idx, const float* __restrict__ x_table,
    int nrows, int sparse)
{
    extern __shared__ float sm[];
    float* sIn = sm;                       // 64*129
    int*   sRow = (int*)(sIn + 64 * 129);  // 64
    float* sU = (float*)(sRow + 64);       // vocab-indexed table / W chunk
    int t = threadIdx.x, lane = t & 31, wid = t >> 5;
    int rg = t >> 4, cg = t & 15;
    int total = sparse ? g_naff : nrows;

    for (int tile = blockIdx.x; tile * 64 < total; tile += gridDim.x) {
        if (t < 64) {
            int idx = tile * 64 + t;
            sRow[t] = (idx < total) ? (sparse ? g_alist[idx] : idx) : -1;
        }
        if (insel < 2) {
            // load the 16KB table: Y1 for L1, x_table for the patch
            const float4* src4 = (insel == 0) ? (const float4*)g_Y1
                                              : (const float4*)x_table;
            float4* s4 = (float4*)sU;
            for (int i = t; i < 1024; i += 256) s4[i] = src4[i];
        }
        __syncthreads();

        for (int rr = wid; rr < 64; rr += 8) {
            int grow = sRow[rr];
            float4 acc = make_float4(0.f, 0.f, 0.f, 0.f);
            if (grow >= 0) {
                if (insel == 0) {
                    int xi = x_idx[grow];
                    acc = *(const float4*)(sU + xi * Dd + lane * 4);
                    acc = gather_tx(sU, x_idx, grow, lane, acc);
                } else if (insel == 2) {
                    acc = *(const float4*)(g_hA + (size_t)grow * Dd + lane * 4);
                    acc = gather_row(g_hA, grow, lane, acc);
                } else {
                    int m = grow / Nn, n = grow - m * Nn;
                    float4 av = *(const float4*)(anchor_table + Dd + lane * 4);
                    int xi = x_idx[n];
                    acc = *(const float4*)(sU + xi * Dd + lane * 4);
                    if (g_flag[grow]) {
                        acc.x = fmaf(acc.x, av.x, acc.x);
                        acc.y = fmaf(acc.y, av.y, acc.y);
                        acc.z = fmaf(acc.z, av.z, acc.z);
                        acc.w = fmaf(acc.w, av.w, acc.w);
                    }
                    acc = gather_xm(sU, x_idx, n, lane, acc, av, m);
                }
            }
            float* d = &sIn[rr * 129 + lane * 4];
            d[0] = acc.x; d[1] = acc.y; d[2] = acc.z; d[3] = acc.w;
        }
        __syncthreads();

        if (mode == 0) {
            // L1: staged values ARE the GEMM result (Y1 table) — direct epilogue.
            // NOTE: sIn row stride 129 floats => scalar loads (516B rows not 16B-aligned).
            for (int idx = t; idx < 2048; idx += 256) {
                int rr = idx >> 5, q = idx & 31;
                int grow = sRow[rr];
                if (grow < 0) continue;
                const float* sp = sIn + rr * 129 + q * 4;
                float4 b4 = *(const float4*)(bias + q * 4);
                float4 v;
                v.x = fmaxf(sp[0] + b4.x, 0.f);
                v.y = fmaxf(sp[1] + b4.y, 0.f);
                v.z = fmaxf(sp[2] + b4.z, 0.f);
                v.w = fmaxf(sp[3] + b4.w, 0.f);
                *(float4*)(g_hA + (size_t)grow * Dd + q * 4) = v;
                *(float4*)(g_hA + (size_t)(grow + Nn) * Dd + q * 4) = v;
            }
            __syncthreads();
            continue;
        }

        float acc[4][8];
#pragma unroll
        for (int r = 0; r < 4; r++)
#pragma unroll
            for (int j = 0; j < 8; j++) acc[r][j] = 0.f;

        for (int kc = 0; kc < 8; kc++) {
            const float4* Ws = (const float4*)(W + kc * 16 * 128);
            ((float4*)sU)[t] = Ws[t];
            ((float4*)sU)[t + 256] = Ws[t + 256];
            __syncthreads();
#pragma unroll
            for (int kk = 0; kk < 16; kk++) {
                float a[4], w[8];
#pragma unroll
                for (int r = 0; r < 4; r++) a[r] = sIn[(rg + 16 * r) * 129 + kc * 16 + kk];
#pragma unroll
                for (int j = 0; j < 8; j++) w[j] = sU[kk * 128 + cg + 16 * j];
#pragma unroll
                for (int r = 0; r < 4; r++)
#pragma unroll
                    for (int j = 0; j < 8; j++) acc[r][j] = fmaf(a[r], w[j], acc[r][j]);
            }
            __syncthreads();
        }

        if (mode == 1) {
#pragma unroll
            for (int r = 0; r < 4; r++) {
                int grow = sRow[rg + 16 * r];
                float p = 0.f;
#pragma unroll
                for (int j = 0; j < 8; j++) {
                    float v = fmaxf(acc[r][j] + bias[cg + 16 * j], 0.f);
                    p = fmaf(v, Wd[cg + 16 * j], p);
                }
#pragma unroll
                for (int o = 8; o > 0; o >>= 1) p += __shfl_xor_sync(0xffffffffu, p, o);
                if (cg == 0 && grow >= 0) g_pred[grow] = p + bd[0];
            }
        } else {
#pragma unroll
            for (int r = 0; r < 4; r++) {
                int rr = rg + 16 * r; int grow = sRow[rr];
                if (grow < 0) continue;
#pragma unroll
                for (int j = 0; j < 8; j++) {
                    float v = fmaxf(acc[r][j] + bias[cg + 16 * j], 0.f);
                    g_hA[(size_t)grow * Dd + cg + 16 * j] = v;
                }
            }
        }
        __syncthreads();
    }
}

// ---------------- tf32 mma.sync GEMM (256 thr, 2 blocks/SM) ----------------
#define SW_STR 136
#define SI_STR 132
#define SMEM_MMA ((128 * SW_STR + 64 * SI_STR) * 4 + 64 * 4)

static __device__ __forceinline__ void mma_tf32(float* c, const uint32_t* a, const uint32_t* b) {
    asm volatile(
        "mma.sync.aligned.m16n8k8.row.col.f32.tf32.tf32.f32 "
        "{%0,%1,%2,%3}, {%4,%5,%6,%7}, {%8,%9}, {%0,%1,%2,%3};"
        : "+f"(c[0]), "+f"(c[1]), "+f"(c[2]), "+f"(c[3])
        : "r"(a[0]), "r"(a[1]), "r"(a[2]), "r"(a[3]), "r"(b[0]), "r"(b[1]));
}

__global__ __launch_bounds__(256) void k_mma(
    int gather, int pool, int insel,
    const float* __restrict__ W, const float* __restrict__ bias,
    const int* __restrict__ batch, int nrows)
{
    extern __shared__ float sm[];
    float* sW = sm;
    float* sIn = sm + 128 * SW_STR;
    int* sRow = (int*)(sIn + 64 * SI_STR);
    const float* in = (insel == 2) ? g_hA : g_hB;
    int t = threadIdx.x, lane = t & 31, wid = t >> 5;
    int gid = lane >> 2, tig = lane & 3;
    int wr = wid >> 2, wc = wid & 3;

    for (int idx = t; idx < 16384; idx += 256) {
        int k = idx >> 7, c = idx & 127;
        sW[k * SW_STR + c] = __uint_as_float(f2tf32(W[idx]));
    }

    int ntile = (nrows + 63) >> 6;
    for (int tile = blockIdx.x; tile < ntile; tile += gridDim.x) {
        if (t < 64) {
            int idx = tile * 64 + t;
            sRow[t] = (idx < nrows) ? idx : -1;
        }
        __syncthreads();

        for (int rr = wid; rr < 64; rr += 8) {
            int grow = sRow[rr];
            float4 acc = make_float4(0.f, 0.f, 0.f, 0.f);
            if (grow >= 0) {
                int m = grow / Nn, n = grow - m * Nn;
                const float* base = in + (size_t)m * Nn * Dd;
                acc = *(const float4*)(base + (size_t)n * Dd + lane * 4);
                if (gather) acc = gather_row(base, n, lane, acc);
            }
            float* d = &sIn[rr * SI_STR + lane * 4];
            d[0] = __uint_as_float(f2tf32(acc.x));
            d[1] = __uint_as_float(f2tf32(acc.y));
            d[2] = __uint_as_float(f2tf32(acc.z));
            d[3] = __uint_as_float(f2tf32(acc.w));
        }
        __syncthreads();

        float c_[2][4][4];
#pragma unroll
        for (int mt = 0; mt < 2; mt++)
#pragma unroll
            for (int nt = 0; nt < 4; nt++)
#pragma unroll
                for (int q = 0; q < 4; q++) c_[mt][nt][q] = 0.f;

#pragma unroll 4
        for (int ks = 0; ks < 16; ks++) {
            int k0 = ks * 8;
            uint32_t a[2][4], b[4][2];
#pragma unroll
            for (int mt = 0; mt < 2; mt++) {
                const float* Ap = sIn + (wr * 32 + mt * 16 + gid) * SI_STR + k0 + tig;
                a[mt][0] = __float_as_uint(Ap[0]);
                a[mt][1] = __float_as_uint(Ap[8 * SI_STR]);
                a[mt][2] = __float_as_uint(Ap[4]);
                a[mt][3] = __float_as_uint(Ap[8 * SI_STR + 4]);
            }
#pragma unroll
            for (int nt = 0; nt < 4; nt++) {
                const float* Bp = sW + (k0 + tig) * SW_STR + wc * 32 + nt * 8 + gid;
                b[nt][0] = __float_as_uint(Bp[0]);
                b[nt][1] = __float_as_uint(Bp[4 * SW_STR]);
            }
#pragma unroll
            for (int mt = 0; mt < 2; mt++)
#pragma unroll
                for (int nt = 0; nt < 4; nt++)
                    mma_tf32(c_[mt][nt], a[mt], b[nt]);
        }
        __syncthreads();

#pragma unroll
        for (int mt = 0; mt < 2; mt++) {
#pragma unroll
            for (int nt = 0; nt < 4; nt++) {
                int col = wc * 32 + nt * 8 + tig * 2;
                int row = wr * 32 + mt * 16 + gid;
                float b0 = bias[col], b1 = bias[col + 1];
                sIn[row * SI_STR + col]           = fmaxf(c_[mt][nt][0] + b0, 0.f);
                sIn[row * SI_STR + col + 1]       = fmaxf(c_[mt][nt][1] + b1, 0.f);
                sIn[(row + 8) * SI_STR + col]     = fmaxf(c_[mt][nt][2] + b0, 0.f);
                sIn[(row + 8) * SI_STR + col + 1] = fmaxf(c_[mt][nt][3] + b1, 0.f);
            }
        }
        __syncthreads();

        if (pool) {
            int col = t & 127, half = t >> 7;
            float s = 0.f; int cur = -1;
            for (int rr = half * 32; rr < half * 32 + 32; rr++) {
                int grow = sRow[rr]; if (grow < 0) continue;
                int m = grow / Nn;
                int key = m * NGg + batch[grow - m * Nn];
                if (key != cur) {
                    if (cur >= 0) atomicAdd(&g_hg[(size_t)cur * Dd + col], s);
                    cur = key; s = 0.f;
                }
                s += sIn[rr * SI_STR + col];
            }
            if (cur >= 0) atomicAdd(&g_hg[(size_t)cur * Dd + col], s);
        } else {
            for (int idx = t; idx < 2048; idx += 256) {
                int rr = idx >> 5, q = idx & 31;
                int grow = sRow[rr];
                if (grow < 0) continue;
                *(float4*)(g_hB + (size_t)grow * Dd + q * 4) =
                    *(float4*)(sIn + rr * SI_STR + q * 4);
            }
        }
        __syncthreads();
    }
}

// ---------------- fused per-graph sampling ----------------
static __device__ __forceinline__ float score_fn(int n, int m, float mx, float ssum,
                                                 unsigned fk0, unsigned fk1) {
    float e = expf(g_pred[n] - mx);
    float p = e / ssum;
    float lp = logf(p + 1e-15f);
    unsigned x0 = 0u, x1 = (unsigned)(m * Nn + n);
    tf2x32(fk0, fk1, x0, x1);
    float u = __uint_as_float((x1 >> 9) | 0x3F800000u) - 1.0f;
    u = fmaxf(u, 0.0f);
    float gum = -logf(-logf(u + 1e-12f) + 1e-12f);
    return lp + gum;
}

__global__ void k_sample(const int* __restrict__ batch, unsigned fk0, unsigned fk1) {
    __shared__ float fb[8];
    __shared__ int ib[8];
    __shared__ int sSE[2];
    __shared__ float sMx, sSum, sBest;
    int g = blockIdx.x, t = threadIdx.x, lane = t & 31, wid = t >> 5;
    if (t < 2) {
        int tgt = g + t;
        int lo = 0, hi = Nn;
        while (lo < hi) { int mid = (lo + hi) >> 1; if (batch[mid] < tgt) lo = mid + 1; else hi = mid; }
        sSE[t] = lo;
    }
    __syncthreads();
    int s0 = sSE[0], s1 = sSE[1];

    float mx = -3.4e38f;
    for (int n = s0 + t; n < s1; n += 256) mx = fmaxf(mx, g_pred[n]);
#pragma unroll
    for (int o = 16; o > 0; o >>= 1) mx = fmaxf(mx, __shfl_xor_sync(0xffffffffu, mx, o));
    if (lane == 0) fb[wid] = mx;
    __syncthreads();
    if (t == 0) { float x = fb[0]; for (int i = 1; i < 8; i++) x = fmaxf(x, fb[i]); sMx = x; }
    __syncthreads();
    float gmx = sMx;

    float sm = 0.f;
    for (int n = s0 + t; n < s1; n += 256) sm += expf(g_pred[n] - gmx);
#pragma unroll
    for (int o = 16; o > 0; o >>= 1) sm += __shfl_xor_sync(0xffffffffu, sm, o);
    if (lane == 0) fb[wid] = sm;
    __syncthreads();
    if (t == 0) { float x = 0.f; for (int i = 0; i < 8; i++) x += fb[i]; sSum = x; }
    __syncthreads();
    float gsum = sSum;

    for (int m = 0; m < Mm; m++) {
        float best = -3.4e38f;
        for (int n = s0 + t; n < s1; n += 256)
            best = fmaxf(best, score_fn(n, m, gmx, gsum, fk0, fk1));
#pragma unroll
        for (int o = 16; o > 0; o >>= 1) best = fmaxf(best, __shfl_xor_sync(0xffffffffu, best, o));
        if (lane == 0) fb[wid] = best;
        __syncthreads();
        if (t == 0) { float x = fb[0]; for (int i = 1; i < 8; i++) x = fmaxf(x, fb[i]); sBest = x; }
        __syncthreads();
        float gb = sBest;
        __syncthreads();

        int cand = Nn;
        for (int n = s0 + t; n < s1; n += 256)
            if (score_fn(n, m, gmx, gsum, fk0, fk1) >= gb) cand = min(cand, n);
#pragma unroll
        for (int o = 16; o > 0; o >>= 1) cand = min(cand, __shfl_xor_sync(0xffffffffu, cand, o));
        if (lane == 0) ib[wid] = cand;
        __syncthreads();
        if (t == 0) {
            int x = ib[0]; for (int i = 1; i < 8; i++) x = min(x, ib[i]);
            if (x < Nn) {
                g_flag[m * Nn + x] = 1;
                if (atomicExch(&g_amark[m * Nn + x], 1) == 0) {
                    int p = atomicAdd(&g_naff, 1);
                    g_alist[p] = m * Nn + x;
                }
            }
        }
        __syncthreads();
    }
}

// single-pass mark: rows whose L1 aggregation changes per m
__global__ void k_mark(const int* __restrict__ esrc, const int* __restrict__ edst) {
    int e = blockIdx.x * blockDim.x + threadIdx.x;
    if (e >= Ee) return;
    int s = esrc[e];
    unsigned char f0 = g_flag[s];
    unsigned char f1 = g_flag[Nn + s];
    if (!(f0 | f1)) return;
    int d = edst[e];
    if (f0 && atomicExch(&g_amark[d], 1) == 0) {
        int p = atomicAdd(&g_naff, 1);
        g_alist[p] = d;
    }
    if (f1 && atomicExch(&g_amark[Nn + d], 1) == 0) {
        int p = atomicAdd(&g_naff, 1);
        g_alist[p] = Nn + d;
    }
}

__global__ void k_final(const float* __restrict__ Wp, const float* __restrict__ bp,
                        float* __restrict__ out) {
    __shared__ float red[128];
    int g = blockIdx.x, t = threadIdx.x;
    int c = g_counts[g]; if (c < 1) c = 1;
    float inv = 1.0f / (float)c;
    float hsum = (g_hg[(size_t)g * Dd + t] + g_hg[((size_t)NGg + g) * Dd + t]) * inv;
    for (int tt = 0; tt < 10; tt++) {
        red[t] = hsum * Wp[t * 10 + tt];
        __syncthreads();
        for (int off = 64; off > 0; off >>= 1) {
            if (t < off) red[t] += red[t + off];
            __syncthreads();
        }
        if (t == 0) out[g * 10 + tt] = red[0] * 0.5f + bp[tt];
        __syncthreads();
    }
}

// ---------------- launch ----------------
static inline int cdiv(int a, int b) { return (a + b - 1) / b; }

extern "C" void kernel_launch(void* const* d_in, const int* in_sizes, int n_in,
                              void* d_out, int out_size) {
    const int*   x_idx        = (const int*)d_in[0];
    const int*   esrc         = (const int*)d_in[1];
    const int*   edst         = (const int*)d_in[2];
    const int*   batch        = (const int*)d_in[3];
    const float* x_table      = (const float*)d_in[4];
    const float* anchor_table = (const float*)d_in[5];
    const float* Wg           = (const float*)d_in[6];
    const float* bg           = (const float*)d_in[7];
    const float* Wn           = (const float*)d_in[8];
    const float* bn           = (const float*)d_in[9];
    const float* Wd           = (const float*)d_in[10];
    const float* bd           = (const float*)d_in[11];
    const float* Wp           = (const float*)d_in[12];
    const float* bp           = (const float*)d_in[13];
    float* out = (float*)d_out;

    unsigned fk0 = 0u, fk1 = 1u;
    tf2x32(0u, 1u, fk0, fk1);

    cudaFuncSetAttribute(k_mma, cudaFuncAttributeMaxDynamicSharedMemorySize, SMEM_MMA);
    cudaFuncSetAttribute(k_fused, cudaFuncAttributeMaxDynamicSharedMemorySize, SM_FUSED_XT);

    // setup
    k_reset<<<cdiv(Mm * Nn, 256), 256>>>();
    k_hist<<<cdiv(Ee, 256), 256>>>(edst, batch);
    k_prep<<<32, 128>>>(x_table, Wg);
    k_scan<<<1, 1024>>>();
    k_fill<<<cdiv(Ee, 256), 256>>>(esrc, edst);

    // pass1 L1: Y1 smem-table gather, NO GEMM, dual-write fp32 hA
    k_fused<<<cdiv(Nn, 64), 256, SM_FUSED_XT>>>(0, 0, Wg, bg, nullptr, nullptr,
                                                nullptr, x_idx, x_table, Nn, 0);
    // pass1 L2: fp32 gather+GEMM + fused pred epilogue
    k_fused<<<cdiv(Nn, 64), 256, SM_FUSED_H>>>(2, 1, Wg + Dd * Dd, bg + Dd, Wd, bd,
                                               nullptr, x_idx, x_table, Nn, 0);

    // anchor sampling + single-pass affected-row marking
    k_sample<<<NGg, 256>>>(batch, fk0, fk1);
    k_mark<<<cdiv(Ee, 256), 256>>>(esrc, edst);

    // pass2 L1: sparse patch, virtual x' from smem vocab table + GEMM (R9 path)
    k_fused<<<148, 256, SM_FUSED_XT>>>(1, 2, Wg, bg, nullptr, nullptr,
                                       anchor_table, x_idx, x_table, 0, 1);

    // pass2 L2 (tf32 mma): hA -> hB
    k_mma<<<296, 256, SMEM_MMA>>>(1, 0, 2, Wg + Dd * Dd, bg + Dd, batch, Mm * Nn);
    // node MLP + pooled epilogue (tf32): hB -> hg
    k_mma<<<296, 256, SMEM_MMA>>>(0, 1, 3, Wn, bn, batch, Mm * Nn);

    // final projection + mean over m
    k_final<<<NGg, 128>>>(Wp, bp, out);
}

// round 16
// speedup vs baseline: 1.6107x; 1.0932x over previous
#include <cuda_runtime.h>
#include <cstdint>

#define Nn  50000
#define Ee  800000
#define NGg 128
#define Dd  128
#define Mm  2
#define SCAN_NB 196   // 196 * 256 = 50176 >= Nn

// ---------------- scratch ----------------
__device__ float g_hA[Mm * Nn * Dd];
__device__ float g_hB[Mm * Nn * Dd];
__device__ float g_Y1[32 * Dd];     // x_table @ Wg1 (precomputed)
__device__ int   g_deg[Nn];
__device__ int   g_rowptr[Nn + 1];
__device__ int   g_cursor[Nn];
__device__ int   g_col[Ee];
__device__ int   g_bsum[SCAN_NB];
__device__ float g_pred[Nn];
__device__ int   g_counts[NGg];
__device__ unsigned char g_flag[Mm * Nn];
__device__ float g_hg[Mm * NGg * Dd];
__device__ int   g_amark[Mm * Nn];
__device__ int   g_alist[Mm * Nn];
__device__ int   g_naff;

// ---------------- threefry2x32 ----------------
static __host__ __device__ inline unsigned rotl32(unsigned v, int r) {
    return (v << r) | (v >> (32 - r));
}
static __host__ __device__ inline void tf2x32(unsigned k0, unsigned k1,
                                              unsigned& x0, unsigned& x1) {
    unsigned k2 = k0 ^ k1 ^ 0x1BD11BDAu;
    x0 += k0; x1 += k1;
#define TFR(r) { x0 += x1; x1 = rotl32(x1, (r)); x1 ^= x0; }
    TFR(13) TFR(15) TFR(26) TFR(6)
    x0 += k1; x1 += k2 + 1u;
    TFR(17) TFR(29) TFR(16) TFR(24)
    x0 += k2; x1 += k0 + 2u;
    TFR(13) TFR(15) TFR(26) TFR(6)
    x0 += k0; x1 += k1 + 3u;
    TFR(17) TFR(29) TFR(16) TFR(24)
    x0 += k1; x1 += k2 + 4u;
    TFR(13) TFR(15) TFR(26) TFR(6)
    x0 += k2; x1 += k0 + 5u;
#undef TFR
}

static __device__ __forceinline__ uint32_t f2tf32(float f) {
    uint32_t r;
    asm("cvt.rna.tf32.f32 %0, %1;" : "=r"(r) : "f"(f));
    return r;
}

// ---------------- fp32 gather (MLP-unrolled) ----------------
static __device__ __forceinline__ float4 gather_row(const float* __restrict__ base,
                                                    int n, int lane, float4 acc) {
    int beg = g_rowptr[n], end = g_rowptr[n + 1];
    float4 a1 = make_float4(0.f, 0.f, 0.f, 0.f);
    float4 a2 = make_float4(0.f, 0.f, 0.f, 0.f);
    float4 a3 = make_float4(0.f, 0.f, 0.f, 0.f);
    for (int b0 = beg; b0 < end; b0 += 32) {
        int lim = end - b0; if (lim > 32) lim = 32;
        int cidx = (lane < lim) ? g_col[b0 + lane] : 0;
        int j = 0;
        for (; j + 4 <= lim; j += 4) {
            int s0 = __shfl_sync(0xffffffffu, cidx, j);
            int s1 = __shfl_sync(0xffffffffu, cidx, j + 1);
            int s2 = __shfl_sync(0xffffffffu, cidx, j + 2);
            int s3 = __shfl_sync(0xffffffffu, cidx, j + 3);
            float4 v0 = *(const float4*)(base + (size_t)s0 * Dd + lane * 4);
            float4 v1 = *(const float4*)(base + (size_t)s1 * Dd + lane * 4);
            float4 v2 = *(const float4*)(base + (size_t)s2 * Dd + lane * 4);
            float4 v3 = *(const float4*)(base + (size_t)s3 * Dd + lane * 4);
            acc.x += v0.x; acc.y += v0.y; acc.z += v0.z; acc.w += v0.w;
            a1.x += v1.x; a1.y += v1.y; a1.z += v1.z; a1.w += v1.w;
            a2.x += v2.x; a2.y += v2.y; a2.z += v2.z; a2.w += v2.w;
            a3.x += v3.x; a3.y += v3.y; a3.z += v3.z; a3.w += v3.w;
        }
        for (; j < lim; j++) {
            int s0 = __shfl_sync(0xffffffffu, cidx, j);
            float4 v0 = *(const float4*)(base + (size_t)s0 * Dd + lane * 4);
            acc.x += v0.x; acc.y += v0.y; acc.z += v0.z; acc.w += v0.w;
        }
    }
    acc.x += a1.x + a2.x + a3.x;
    acc.y += a1.y + a2.y + a3.y;
    acc.z += a1.z + a2.z + a3.z;
    acc.w += a1.w + a2.w + a3.w;
    return acc;
}

// gather from smem vocab-indexed table: per edge only a 4B x_idx load from global
static __device__ __forceinline__ float4 gather_tx(const float* __restrict__ sXT,
                                                   const int* __restrict__ x_idx,
                                                   int n, int lane, float4 acc) {
    int beg = g_rowptr[n], end = g_rowptr[n + 1];
    float4 a1 = make_float4(0.f, 0.f, 0.f, 0.f);
    float4 a2 = make_float4(0.f, 0.f, 0.f, 0.f);
    float4 a3 = make_float4(0.f, 0.f, 0.f, 0.f);
    for (int b0 = beg; b0 < end; b0 += 32) {
        int lim = end - b0; if (lim > 32) lim = 32;
        int xv = 0;
        if (lane < lim) xv = x_idx[g_col[b0 + lane]];
        int j = 0;
        for (; j + 4 <= lim; j += 4) {
            int s0 = __shfl_sync(0xffffffffu, xv, j);
            int s1 = __shfl_sync(0xffffffffu, xv, j + 1);
            int s2 = __shfl_sync(0xffffffffu, xv, j + 2);
            int s3 = __shfl_sync(0xffffffffu, xv, j + 3);
            float4 v0 = *(const float4*)(sXT + s0 * Dd + lane * 4);
            float4 v1 = *(const float4*)(sXT + s1 * Dd + lane * 4);
            float4 v2 = *(const float4*)(sXT + s2 * Dd + lane * 4);
            float4 v3 = *(const float4*)(sXT + s3 * Dd + lane * 4);
            acc.x += v0.x; acc.y += v0.y; acc.z += v0.z; acc.w += v0.w;
            a1.x += v1.x; a1.y += v1.y; a1.z += v1.z; a1.w += v1.w;
            a2.x += v2.x; a2.y += v2.y; a2.z += v2.z; a2.w += v2.w;
            a3.x += v3.x; a3.y += v3.y; a3.z += v3.z; a3.w += v3.w;
        }
        for (; j < lim; j++) {
            int s0 = __shfl_sync(0xffffffffu, xv, j);
            float4 v0 = *(const float4*)(sXT + s0 * Dd + lane * 4);
            acc.x += v0.x; acc.y += v0.y; acc.z += v0.z; acc.w += v0.w;
        }
    }
    acc.x += a1.x + a2.x + a3.x;
    acc.y += a1.y + a2.y + a3.y;
    acc.z += a1.z + a2.z + a3.z;
    acc.w += a1.w + a2.w + a3.w;
    return acc;
}

// virtual x' gather: smem vocab row + flag-predicated anchor scaling (sparse patch)
static __device__ __forceinline__ float4 gather_xm(const float* __restrict__ sXT,
                                                   const int* __restrict__ x_idx,
                                                   int n, int lane, float4 acc,
                                                   float4 av, int m) {
    int beg = g_rowptr[n], end = g_rowptr[n + 1];
    for (int b0 = beg; b0 < end; b0 += 32) {
        int lim = end - b0; if (lim > 32) lim = 32;
        int pk = 0;
        if (lane < lim) {
            int s = g_col[b0 + lane];
            pk = x_idx[s] | ((int)g_flag[m * Nn + s] << 8);
        }
        for (int j = 0; j < lim; j++) {
            int p = __shfl_sync(0xffffffffu, pk, j);
            float4 v = *(const float4*)(sXT + (p & 255) * Dd + lane * 4);
            if (p >> 8) {
                v.x = fmaf(v.x, av.x, v.x);
                v.y = fmaf(v.y, av.y, v.y);
                v.z = fmaf(v.z, av.z, v.z);
                v.w = fmaf(v.w, av.w, v.w);
            }
            acc.x += v.x; acc.y += v.y; acc.z += v.z; acc.w += v.w;
        }
    }
    return acc;
}

// ---------------- small kernels ----------------
__global__ void k_reset() {
    int i = blockIdx.x * blockDim.x + threadIdx.x;
    if (i < Mm * Nn) { g_flag[i] = 0; g_amark[i] = 0; }
    if (i < Nn) { g_deg[i] = 0; g_cursor[i] = 0; }
    if (i < Mm * NGg * Dd) g_hg[i] = 0.f;
    if (i < NGg) g_counts[i] = 0;
    if (i == 0) g_naff = 0;
}

// hist + per-graph node counts (fused)
__global__ void k_hist(const int* __restrict__ edst, const int* __restrict__ batch) {
    int e = blockIdx.x * blockDim.x + threadIdx.x;
    if (e < Ee) atomicAdd(&g_deg[edst[e]], 1);
    if (e < Nn) atomicAdd(&g_counts[batch[e]], 1);
}

// Y1[v] = x_table[v] @ Wg1  (one block per vocab row)
__global__ __launch_bounds__(128) void k_prep(const float* __restrict__ x_table,
                                              const float* __restrict__ Wg) {
    __shared__ float sx[Dd];
    int v = blockIdx.x, c = threadIdx.x;
    sx[c] = x_table[v * Dd + c];
    __syncthreads();
    float y = 0.f;
#pragma unroll 8
    for (int k = 0; k < Dd; k++) y = fmaf(sx[k], Wg[k * Dd + c], y);
    g_Y1[v * Dd + c] = y;
}

// ---------------- multi-block exclusive scan of g_deg -> g_rowptr ----------------
__global__ __launch_bounds__(256) void k_scanA() {
    __shared__ int ss[256];
    int b = blockIdx.x, t = threadIdx.x;
    int i = b * 256 + t;
    int v = (i < Nn) ? g_deg[i] : 0;
    ss[t] = v;
    __syncthreads();
    for (int off = 1; off < 256; off <<= 1) {
        int x = (t >= off) ? ss[t - off] : 0;
        __syncthreads();
        ss[t] += x;
        __syncthreads();
    }
    if (i < Nn) g_rowptr[i] = ss[t] - v;     // block-local exclusive prefix
    if (t == 255) g_bsum[b] = ss[255];       // block total
}

__global__ __launch_bounds__(256) void k_scanB() {
    __shared__ int ss[256];
    int t = threadIdx.x;
    int v = (t < SCAN_NB) ? g_bsum[t] : 0;
    ss[t] = v;
    __syncthreads();
    for (int off = 1; off < 256; off <<= 1) {
        int x = (t >= off) ? ss[t - off] : 0;
        __syncthreads();
        ss[t] += x;
        __syncthreads();
    }
    if (t < SCAN_NB) g_bsum[t] = ss[t] - v;  // exclusive block offsets
    if (t == 255) g_rowptr[Nn] = ss[255];    // total (= Ee)
}

__global__ __launch_bounds__(256) void k_scanC() {
    int b = blockIdx.x;
    int i = b * 256 + threadIdx.x;
    if (i < Nn) g_rowptr[i] += g_bsum[b];
}

__global__ void k_fill(const int* __restrict__ esrc, const int* __restrict__ edst) {
    int e = blockIdx.x * blockDim.x + threadIdx.x;
    if (e >= Ee) return;
    int d = edst[e];
    int p = atomicAdd(&g_cursor[d], 1);
    g_col[g_rowptr[d] + p] = esrc[e];
}

// ---------------- fp32 fused gather(+GEMM) ----------------
// insel: 0 = Y1 from smem table (pass1 L1, NO GEMM — writes relu(sum+bg) dual)
//        1 = virtual x' from smem vocab table (sparse patch, with GEMM)
//        2 = g_hA (pass1 L2, with GEMM)
// mode : 0 = L1 direct write (dual slices)   1 = pred epilogue   2 = patch write
#define SM_FUSED_XT ((64 * 129 + 64 + 32 * 128) * 4)
#define SM_FUSED_H  ((64 * 129 + 64 + 16 * 128) * 4)
__global__ __launch_bounds__(256) void k_fused(
    int insel, int mode,
    const float* __restrict__ W, const float* __restrict__ bias,
    const float* __restrict__ Wd, const float* __restrict__ bd,
    const float* __restrict__ anchor_table,
    const int* __restrict__ x_idx, const float* __restrict__ x_table,
    int nrows, int sparse)
{
    extern __shared__ float sm[];
    float* sIn = sm;                       // 64*129
    int*   sRow = (int*)(sIn + 64 * 129);  // 64
    float* sU = (float*)(sRow + 64);       // vocab-indexed table / W chunk
    int t = threadIdx.x, lane = t & 31, wid = t >> 5;
    int rg = t >> 4, cg = t & 15;
    int total = sparse ? g_naff : nrows;

    for (int tile = blockIdx.x; tile * 64 < total; tile += gridDim.x) {
        if (t < 64) {
            int idx = tile * 64 + t;
            sRow[t] = (idx < total) ? (sparse ? g_alist[idx] : idx) : -1;
        }
        if (insel < 2) {
            // load the 16KB table: Y1 for L1, x_table for the patch
            const float4* src4 = (insel == 0) ? (const float4*)g_Y1
                                              : (const float4*)x_table;
            float4* s4 = (float4*)sU;
            for (int i = t; i < 1024; i += 256) s4[i] = src4[i];
        }
        __syncthreads();

        for (int rr = wid; rr < 64; rr += 8) {
            int grow = sRow[rr];
            float4 acc = make_float4(0.f, 0.f, 0.f, 0.f);
            if (grow >= 0) {
                if (insel == 0) {
                    int xi = x_idx[grow];
                    acc = *(const float4*)(sU + xi * Dd + lane * 4);
                    acc = gather_tx(sU, x_idx, grow, lane, acc);
                } else if (insel == 2) {
                    acc = *(const float4*)(g_hA + (size_t)grow * Dd + lane * 4);
                    acc = gather_row(g_hA, grow, lane, acc);
                } else {
                    int m = grow / Nn, n = grow - m * Nn;
                    float4 av = *(const float4*)(anchor_table + Dd + lane * 4);
                    int xi = x_idx[n];
                    acc = *(const float4*)(sU + xi * Dd + lane * 4);
                    if (g_flag[grow]) {
                        acc.x = fmaf(acc.x, av.x, acc.x);
                        acc.y = fmaf(acc.y, av.y, acc.y);
                        acc.z = fmaf(acc.z, av.z, acc.z);
                        acc.w = fmaf(acc.w, av.w, acc.w);
                    }
                    acc = gather_xm(sU, x_idx, n, lane, acc, av, m);
                }
            }
            float* d = &sIn[rr * 129 + lane * 4];
            d[0] = acc.x; d[1] = acc.y; d[2] = acc.z; d[3] = acc.w;
        }
        __syncthreads();

        if (mode == 0) {
            // L1: staged values ARE the GEMM result (Y1 table) — direct epilogue.
            // NOTE: sIn row stride 129 floats => scalar loads (516B rows not 16B-aligned).
            for (int idx = t; idx < 2048; idx += 256) {
                int rr = idx >> 5, q = idx & 31;
                int grow = sRow[rr];
                if (grow < 0) continue;
                const float* sp = sIn + rr * 129 + q * 4;
                float4 b4 = *(const float4*)(bias + q * 4);
                float4 v;
                v.x = fmaxf(sp[0] + b4.x, 0.f);
                v.y = fmaxf(sp[1] + b4.y, 0.f);
                v.z = fmaxf(sp[2] + b4.z, 0.f);
                v.w = fmaxf(sp[3] + b4.w, 0.f);
                *(float4*)(g_hA + (size_t)grow * Dd + q * 4) = v;
                *(float4*)(g_hA + (size_t)(grow + Nn) * Dd + q * 4) = v;
            }
            __syncthreads();
            continue;
        }

        float acc[4][8];
#pragma unroll
        for (int r = 0; r < 4; r++)
#pragma unroll
            for (int j = 0; j < 8; j++) acc[r][j] = 0.f;

        for (int kc = 0; kc < 8; kc++) {
            const float4* Ws = (const float4*)(W + kc * 16 * 128);
            ((float4*)sU)[t] = Ws[t];
            ((float4*)sU)[t + 256] = Ws[t + 256];
            __syncthreads();
#pragma unroll
            for (int kk = 0; kk < 16; kk++) {
                float a[4], w[8];
#pragma unroll
                for (int r = 0; r < 4; r++) a[r] = sIn[(rg + 16 * r) * 129 + kc * 16 + kk];
#pragma unroll
                for (int j = 0; j < 8; j++) w[j] = sU[kk * 128 + cg + 16 * j];
#pragma unroll
                for (int r = 0; r < 4; r++)
#pragma unroll
                    for (int j = 0; j < 8; j++) acc[r][j] = fmaf(a[r], w[j], acc[r][j]);
            }
            __syncthreads();
        }

        if (mode == 1) {
#pragma unroll
            for (int r = 0; r < 4; r++) {
                int grow = sRow[rg + 16 * r];
                float p = 0.f;
#pragma unroll
                for (int j = 0; j < 8; j++) {
                    float v = fmaxf(acc[r][j] + bias[cg + 16 * j], 0.f);
                    p = fmaf(v, Wd[cg + 16 * j], p);
                }
#pragma unroll
                for (int o = 8; o > 0; o >>= 1) p += __shfl_xor_sync(0xffffffffu, p, o);
                if (cg == 0 && grow >= 0) g_pred[grow] = p + bd[0];
            }
        } else {
#pragma unroll
            for (int r = 0; r < 4; r++) {
                int rr = rg + 16 * r; int grow = sRow[rr];
                if (grow < 0) continue;
#pragma unroll
                for (int j = 0; j < 8; j++) {
                    float v = fmaxf(acc[r][j] + bias[cg + 16 * j], 0.f);
                    g_hA[(size_t)grow * Dd + cg + 16 * j] = v;
                }
            }
        }
        __syncthreads();
    }
}

// ---------------- tf32 mma.sync GEMM (256 thr, 2 blocks/SM) ----------------
#define SW_STR 136
#define SI_STR 132
#define SMEM_MMA ((128 * SW_STR + 64 * SI_STR) * 4 + 64 * 4)

static __device__ __forceinline__ void mma_tf32(float* c, const uint32_t* a, const uint32_t* b) {
    asm volatile(
        "mma.sync.aligned.m16n8k8.row.col.f32.tf32.tf32.f32 "
        "{%0,%1,%2,%3}, {%4,%5,%6,%7}, {%8,%9}, {%0,%1,%2,%3};"
        : "+f"(c[0]), "+f"(c[1]), "+f"(c[2]), "+f"(c[3])
        : "r"(a[0]), "r"(a[1]), "r"(a[2]), "r"(a[3]), "r"(b[0]), "r"(b[1]));
}

__global__ __launch_bounds__(256) void k_mma(
    int gather, int pool, int insel,
    const float* __restrict__ W, const float* __restrict__ bias,
    const int* __restrict__ batch, int nrows)
{
    extern __shared__ float sm[];
    float* sW = sm;
    float* sIn = sm + 128 * SW_STR;
    int* sRow = (int*)(sIn + 64 * SI_STR);
    const float* in = (insel == 2) ? g_hA : g_hB;
    int t = threadIdx.x, lane = t & 31, wid = t >> 5;
    int gid = lane >> 2, tig = lane & 3;
    int wr = wid >> 2, wc = wid & 3;

    for (int idx = t; idx < 16384; idx += 256) {
        int k = idx >> 7, c = idx & 127;
        sW[k * SW_STR + c] = __uint_as_float(f2tf32(W[idx]));
    }

    int ntile = (nrows + 63) >> 6;
    for (int tile = blockIdx.x; tile < ntile; tile += gridDim.x) {
        if (t < 64) {
            int idx = tile * 64 + t;
            sRow[t] = (idx < nrows) ? idx : -1;
        }
        __syncthreads();

        for (int rr = wid; rr < 64; rr += 8) {
            int grow = sRow[rr];
            float4 acc = make_float4(0.f, 0.f, 0.f, 0.f);
            if (grow >= 0) {
                int m = grow / Nn, n = grow - m * Nn;
                const float* base = in + (size_t)m * Nn * Dd;
                acc = *(const float4*)(base + (size_t)n * Dd + lane * 4);
                if (gather) acc = gather_row(base, n, lane, acc);
            }
            float* d = &sIn[rr * SI_STR + lane * 4];
            d[0] = __uint_as_float(f2tf32(acc.x));
            d[1] = __uint_as_float(f2tf32(acc.y));
            d[2] = __uint_as_float(f2tf32(acc.z));
            d[3] = __uint_as_float(f2tf32(acc.w));
        }
        __syncthreads();

        float c_[2][4][4];
#pragma unroll
        for (int mt = 0; mt < 2; mt++)
#pragma unroll
            for (int nt = 0; nt < 4; nt++)
#pragma unroll
                for (int q = 0; q < 4; q++) c_[mt][nt][q] = 0.f;

#pragma unroll 4
        for (int ks = 0; ks < 16; ks++) {
            int k0 = ks * 8;
            uint32_t a[2][4], b[4][2];
#pragma unroll
            for (int mt = 0; mt < 2; mt++) {
                const float* Ap = sIn + (wr * 32 + mt * 16 + gid) * SI_STR + k0 + tig;
                a[mt][0] = __float_as_uint(Ap[0]);
                a[mt][1] = __float_as_uint(Ap[8 * SI_STR]);
                a[mt][2] = __float_as_uint(Ap[4]);
                a[mt][3] = __float_as_uint(Ap[8 * SI_STR + 4]);
            }
#pragma unroll
            for (int nt = 0; nt < 4; nt++) {
                const float* Bp = sW + (k0 + tig) * SW_STR + wc * 32 + nt * 8 + gid;
                b[nt][0] = __float_as_uint(Bp[0]);
                b[nt][1] = __float_as_uint(Bp[4 * SW_STR]);
            }
#pragma unroll
            for (int mt = 0; mt < 2; mt++)
#pragma unroll
                for (int nt = 0; nt < 4; nt++)
                    mma_tf32(c_[mt][nt], a[mt], b[nt]);
        }
        __syncthreads();

#pragma unroll
        for (int mt = 0; mt < 2; mt++) {
#pragma unroll
            for (int nt = 0; nt < 4; nt++) {
                int col = wc * 32 + nt * 8 + tig * 2;
                int row = wr * 32 + mt * 16 + gid;
                float b0 = bias[col], b1 = bias[col + 1];
                sIn[row * SI_STR + col]           = fmaxf(c_[mt][nt][0] + b0, 0.f);
                sIn[row * SI_STR + col + 1]       = fmaxf(c_[mt][nt][1] + b1, 0.f);
                sIn[(row + 8) * SI_STR + col]     = fmaxf(c_[mt][nt][2] + b0, 0.f);
                sIn[(row + 8) * SI_STR + col + 1] = fmaxf(c_[mt][nt][3] + b1, 0.f);
            }
        }
        __syncthreads();

        if (pool) {
            int col = t & 127, half = t >> 7;
            float s = 0.f; int cur = -1;
            for (int rr = half * 32; rr < half * 32 + 32; rr++) {
                int grow = sRow[rr]; if (grow < 0) continue;
                int m = grow / Nn;
                int key = m * NGg + batch[grow - m * Nn];
                if (key != cur) {
                    if (cur >= 0) atomicAdd(&g_hg[(size_t)cur * Dd + col], s);
                    cur = key; s = 0.f;
                }
                s += sIn[rr * SI_STR + col];
            }
            if (cur >= 0) atomicAdd(&g_hg[(size_t)cur * Dd + col], s);
        } else {
            for (int idx = t; idx < 2048; idx += 256) {
                int rr = idx >> 5, q = idx & 31;
                int grow = sRow[rr];
                if (grow < 0) continue;
                *(float4*)(g_hB + (size_t)grow * Dd + q * 4) =
                    *(float4*)(sIn + rr * SI_STR + q * 4);
            }
        }
        __syncthreads();
    }
}

// ---------------- fused per-graph sampling ----------------
static __device__ __forceinline__ float score_fn(int n, int m, float mx, float ssum,
                                                 unsigned fk0, unsigned fk1) {
    float e = expf(g_pred[n] - mx);
    float p = e / ssum;
    float lp = logf(p + 1e-15f);
    unsigned x0 = 0u, x1 = (unsigned)(m * Nn + n);
    tf2x32(fk0, fk1, x0, x1);
    float u = __uint_as_float((x1 >> 9) | 0x3F800000u) - 1.0f;
    u = fmaxf(u, 0.0f);
    float gum = -logf(-logf(u + 1e-12f) + 1e-12f);
    return lp + gum;
}

__global__ void k_sample(const int* __restrict__ batch, unsigned fk0, unsigned fk1) {
    __shared__ float fb[8];
    __shared__ int ib[8];
    __shared__ int sSE[2];
    __shared__ float sMx, sSum, sBest;
    int g = blockIdx.x, t = threadIdx.x, lane = t & 31, wid = t >> 5;
    if (t < 2) {
        int tgt = g + t;
        int lo = 0, hi = Nn;
        while (lo < hi) { int mid = (lo + hi) >> 1; if (batch[mid] < tgt) lo = mid + 1; else hi = mid; }
        sSE[t] = lo;
    }
    __syncthreads();
    int s0 = sSE[0], s1 = sSE[1];

    float mx = -3.4e38f;
    for (int n = s0 + t; n < s1; n += 256) mx = fmaxf(mx, g_pred[n]);
#pragma unroll
    for (int o = 16; o > 0; o >>= 1) mx = fmaxf(mx, __shfl_xor_sync(0xffffffffu, mx, o));
    if (lane == 0) fb[wid] = mx;
    __syncthreads();
    if (t == 0) { float x = fb[0]; for (int i = 1; i < 8; i++) x = fmaxf(x, fb[i]); sMx = x; }
    __syncthreads();
    float gmx = sMx;

    float sm = 0.f;
    for (int n = s0 + t; n < s1; n += 256) sm += expf(g_pred[n] - gmx);
#pragma unroll
    for (int o = 16; o > 0; o >>= 1) sm += __shfl_xor_sync(0xffffffffu, sm, o);
    if (lane == 0) fb[wid] = sm;
    __syncthreads();
    if (t == 0) { float x = 0.f; for (int i = 0; i < 8; i++) x += fb[i]; sSum = x; }
    __syncthreads();
    float gsum = sSum;

    for (int m = 0; m < Mm; m++) {
        float best = -3.4e38f;
        for (int n = s0 + t; n < s1; n += 256)
            best = fmaxf(best, score_fn(n, m, gmx, gsum, fk0, fk1));
#pragma unroll
        for (int o = 16; o > 0; o >>= 1) best = fmaxf(best, __shfl_xor_sync(0xffffffffu, best, o));
        if (lane == 0) fb[wid] = best;
        __syncthreads();
        if (t == 0) { float x = fb[0]; for (int i = 1; i < 8; i++) x = fmaxf(x, fb[i]); sBest = x; }
        __syncthreads();
        float gb = sBest;
        __syncthreads();

        int cand = Nn;
        for (int n = s0 + t; n < s1; n += 256)
            if (score_fn(n, m, gmx, gsum, fk0, fk1) >= gb) cand = min(cand, n);
#pragma unroll
        for (int o = 16; o > 0; o >>= 1) cand = min(cand, __shfl_xor_sync(0xffffffffu, cand, o));
        if (lane == 0) ib[wid] = cand;
        __syncthreads();
        if (t == 0) {
            int x = ib[0]; for (int i = 1; i < 8; i++) x = min(x, ib[i]);
            if (x < Nn) {
                g_flag[m * Nn + x] = 1;
                if (atomicExch(&g_amark[m * Nn + x], 1) == 0) {
                    int p = atomicAdd(&g_naff, 1);
                    g_alist[p] = m * Nn + x;
                }
            }
        }
        __syncthreads();
    }
}

// single-pass mark: rows whose L1 aggregation changes per m
__global__ void k_mark(const int* __restrict__ esrc, const int* __restrict__ edst) {
    int e = blockIdx.x * blockDim.x + threadIdx.x;
    if (e >= Ee) return;
    int s = esrc[e];
    unsigned char f0 = g_flag[s];
    unsigned char f1 = g_flag[Nn + s];
    if (!(f0 | f1)) return;
    int d = edst[e];
    if (f0 && atomicExch(&g_amark[d], 1) == 0) {
        int p = atomicAdd(&g_naff, 1);
        g_alist[p] = d;
    }
    if (f1 && atomicExch(&g_amark[Nn + d], 1) == 0) {
        int p = atomicAdd(&g_naff, 1);
        g_alist[p] = Nn + d;
    }
}

__global__ void k_final(const float* __restrict__ Wp, const float* __restrict__ bp,
                        float* __restrict__ out) {
    __shared__ float red[128];
    int g = blockIdx.x, t = threadIdx.x;
    int c = g_counts[g]; if (c < 1) c = 1;
    float inv = 1.0f / (float)c;
    float hsum = (g_hg[(size_t)g * Dd + t] + g_hg[((size_t)NGg + g) * Dd + t]) * inv;
    for (int tt = 0; tt < 10; tt++) {
        red[t] = hsum * Wp[t * 10 + tt];
        __syncthreads();
        for (int off = 64; off > 0; off >>= 1) {
            if (t < off) red[t] += red[t + off];
            __syncthreads();
        }
        if (t == 0) out[g * 10 + tt] = red[0] * 0.5f + bp[tt];
        __syncthreads();
    }
}

// ---------------- launch ----------------
static inline int cdiv(int a, int b) { return (a + b - 1) / b; }

extern "C" void kernel_launch(void* const* d_in, const int* in_sizes, int n_in,
                              void* d_out, int out_size) {
    const int*   x_idx        = (const int*)d_in[0];
    const int*   esrc         = (const int*)d_in[1];
    const int*   edst         = (const int*)d_in[2];
    const int*   batch        = (const int*)d_in[3];
    const float* x_table      = (const float*)d_in[4];
    const float* anchor_table = (const float*)d_in[5];
    const float* Wg           = (const float*)d_in[6];
    const float* bg           = (const float*)d_in[7];
    const float* Wn           = (const float*)d_in[8];
    const float* bn           = (const float*)d_in[9];
    const float* Wd           = (const float*)d_in[10];
    const float* bd           = (const float*)d_in[11];
    const float* Wp           = (const float*)d_in[12];
    const float* bp           = (const float*)d_in[13];
    float* out = (float*)d_out;

    unsigned fk0 = 0u, fk1 = 1u;
    tf2x32(0u, 1u, fk0, fk1);

    cudaFuncSetAttribute(k_mma, cudaFuncAttributeMaxDynamicSharedMemorySize, SMEM_MMA);
    cudaFuncSetAttribute(k_fused, cudaFuncAttributeMaxDynamicSharedMemorySize, SM_FUSED_XT);

    // setup (multi-block scan replaces the 47us single-block scan)
    k_reset<<<cdiv(Mm * Nn, 256), 256>>>();
    k_hist<<<cdiv(Ee, 256), 256>>>(edst, batch);
    k_prep<<<32, 128>>>(x_table, Wg);
    k_scanA<<<SCAN_NB, 256>>>();
    k_scanB<<<1, 256>>>();
    k_scanC<<<SCAN_NB, 256>>>();
    k_fill<<<cdiv(Ee, 256), 256>>>(esrc, edst);

    // pass1 L1: Y1 smem-table gather, NO GEMM, dual-write fp32 hA
    k_fused<<<cdiv(Nn, 64), 256, SM_FUSED_XT>>>(0, 0, Wg, bg, nullptr, nullptr,
                                                nullptr, x_idx, x_table, Nn, 0);
    // pass1 L2: fp32 gather+GEMM + fused pred epilogue
    k_fused<<<cdiv(Nn, 64), 256, SM_FUSED_H>>>(2, 1, Wg + Dd * Dd, bg + Dd, Wd, bd,
                                               nullptr, x_idx, x_table, Nn, 0);

    // anchor sampling + single-pass affected-row marking
    k_sample<<<NGg, 256>>>(batch, fk0, fk1);
    k_mark<<<cdiv(Ee, 256), 256>>>(esrc, edst);

    // pass2 L1: sparse patch, virtual x' from smem vocab table + GEMM (R9 path)
    k_fused<<<148, 256, SM_FUSED_XT>>>(1, 2, Wg, bg, nullptr, nullptr,
                                       anchor_table, x_idx, x_table, 0, 1);

    // pass2 L2 (tf32 mma): hA -> hB
    k_mma<<<296, 256, SMEM_MMA>>>(1, 0, 2, Wg + Dd * Dd, bg + Dd, batch, Mm * Nn);
    // node MLP + pooled epilogue (tf32): hB -> hg
    k_mma<<<296, 256, SMEM_MMA>>>(0, 1, 3, Wn, bn, batch, Mm * Nn);

    // final projection + mean over m
    k_final<<<NGg, 128>>>(Wp, bp, out);
}

// round 17
// speedup vs baseline: 1.7625x; 1.0942x over previous
#include <cuda_runtime.h>
#include <cstdint>

#define Nn  50000
#define Ee  800000
#define NGg 128
#define Dd  128
#define Mm  2
#define SCAN_NB 196   // 196 * 256 = 50176 >= Nn

// ---------------- scratch ----------------
__device__ float g_hAs[Nn * Dd];        // shared (unpatched) L1 output
__device__ float g_hA[Mm * Nn * Dd];    // per-m overlay: only patched rows valid
__device__ float g_hB[Mm * Nn * Dd];
__device__ float g_Y1[32 * Dd];         // x_table @ Wg1 (precomputed)
__device__ int   g_deg[Nn];
__device__ int   g_rowptr[Nn + 1];
__device__ int   g_cursor[Nn];
__device__ int   g_col[Ee];
__device__ int   g_bsum[SCAN_NB];
__device__ float g_pred[Nn];
__device__ int   g_counts[NGg];
__device__ unsigned char g_flag[Mm * Nn];
__device__ int   g_pm[Nn];              // bit m: node patched in slice m
__device__ float g_hg[Mm * NGg * Dd];
__device__ int   g_amark[Mm * Nn];
__device__ int   g_alist[Mm * Nn];
__device__ int   g_naff;

// ---------------- threefry2x32 ----------------
static __host__ __device__ inline unsigned rotl32(unsigned v, int r) {
    return (v << r) | (v >> (32 - r));
}
static __host__ __device__ inline void tf2x32(unsigned k0, unsigned k1,
                                              unsigned& x0, unsigned& x1) {
    unsigned k2 = k0 ^ k1 ^ 0x1BD11BDAu;
    x0 += k0; x1 += k1;
#define TFR(r) { x0 += x1; x1 = rotl32(x1, (r)); x1 ^= x0; }
    TFR(13) TFR(15) TFR(26) TFR(6)
    x0 += k1; x1 += k2 + 1u;
    TFR(17) TFR(29) TFR(16) TFR(24)
    x0 += k2; x1 += k0 + 2u;
    TFR(13) TFR(15) TFR(26) TFR(6)
    x0 += k0; x1 += k1 + 3u;
    TFR(17) TFR(29) TFR(16) TFR(24)
    x0 += k1; x1 += k2 + 4u;
    TFR(13) TFR(15) TFR(26) TFR(6)
    x0 += k2; x1 += k0 + 5u;
#undef TFR
}

static __device__ __forceinline__ uint32_t f2tf32(float f) {
    uint32_t r;
    asm("cvt.rna.tf32.f32 %0, %1;" : "=r"(r) : "f"(f));
    return r;
}

// ---------------- fp32 gather (MLP-unrolled) ----------------
static __device__ __forceinline__ float4 gather_row(const float* __restrict__ base,
                                                    int n, int lane, float4 acc) {
    int beg = g_rowptr[n], end = g_rowptr[n + 1];
    float4 a1 = make_float4(0.f, 0.f, 0.f, 0.f);
    float4 a2 = make_float4(0.f, 0.f, 0.f, 0.f);
    float4 a3 = make_float4(0.f, 0.f, 0.f, 0.f);
    for (int b0 = beg; b0 < end; b0 += 32) {
        int lim = end - b0; if (lim > 32) lim = 32;
        int cidx = (lane < lim) ? g_col[b0 + lane] : 0;
        int j = 0;
        for (; j + 4 <= lim; j += 4) {
            int s0 = __shfl_sync(0xffffffffu, cidx, j);
            int s1 = __shfl_sync(0xffffffffu, cidx, j + 1);
            int s2 = __shfl_sync(0xffffffffu, cidx, j + 2);
            int s3 = __shfl_sync(0xffffffffu, cidx, j + 3);
            float4 v0 = *(const float4*)(base + (size_t)s0 * Dd + lane * 4);
            float4 v1 = *(const float4*)(base + (size_t)s1 * Dd + lane * 4);
            float4 v2 = *(const float4*)(base + (size_t)s2 * Dd + lane * 4);
            float4 v3 = *(const float4*)(base + (size_t)s3 * Dd + lane * 4);
            acc.x += v0.x; acc.y += v0.y; acc.z += v0.z; acc.w += v0.w;
            a1.x += v1.x; a1.y += v1.y; a1.z += v1.z; a1.w += v1.w;
            a2.x += v2.x; a2.y += v2.y; a2.z += v2.z; a2.w += v2.w;
            a3.x += v3.x; a3.y += v3.y; a3.z += v3.z; a3.w += v3.w;
        }
        for (; j < lim; j++) {
            int s0 = __shfl_sync(0xffffffffu, cidx, j);
            float4 v0 = *(const float4*)(base + (size_t)s0 * Dd + lane * 4);
            acc.x += v0.x; acc.y += v0.y; acc.z += v0.z; acc.w += v0.w;
        }
    }
    acc.x += a1.x + a2.x + a3.x;
    acc.y += a1.y + a2.y + a3.y;
    acc.z += a1.z + a2.z + a3.z;
    acc.w += a1.w + a2.w + a3.w;
    return acc;
}

// gather from smem vocab-indexed table: per edge only a 4B x_idx load from global
static __device__ __forceinline__ float4 gather_tx(const float* __restrict__ sXT,
                                                   const int* __restrict__ x_idx,
                                                   int n, int lane, float4 acc) {
    int beg = g_rowptr[n], end = g_rowptr[n + 1];
    float4 a1 = make_float4(0.f, 0.f, 0.f, 0.f);
    float4 a2 = make_float4(0.f, 0.f, 0.f, 0.f);
    float4 a3 = make_float4(0.f, 0.f, 0.f, 0.f);
    for (int b0 = beg; b0 < end; b0 += 32) {
        int lim = end - b0; if (lim > 32) lim = 32;
        int xv = 0;
        if (lane < lim) xv = x_idx[g_col[b0 + lane]];
        int j = 0;
        for (; j + 4 <= lim; j += 4) {
            int s0 = __shfl_sync(0xffffffffu, xv, j);
            int s1 = __shfl_sync(0xffffffffu, xv, j + 1);
            int s2 = __shfl_sync(0xffffffffu, xv, j + 2);
            int s3 = __shfl_sync(0xffffffffu, xv, j + 3);
            float4 v0 = *(const float4*)(sXT + s0 * Dd + lane * 4);
            float4 v1 = *(const float4*)(sXT + s1 * Dd + lane * 4);
            float4 v2 = *(const float4*)(sXT + s2 * Dd + lane * 4);
            float4 v3 = *(const float4*)(sXT + s3 * Dd + lane * 4);
            acc.x += v0.x; acc.y += v0.y; acc.z += v0.z; acc.w += v0.w;
            a1.x += v1.x; a1.y += v1.y; a1.z += v1.z; a1.w += v1.w;
            a2.x += v2.x; a2.y += v2.y; a2.z += v2.z; a2.w += v2.w;
            a3.x += v3.x; a3.y += v3.y; a3.z += v3.z; a3.w += v3.w;
        }
        for (; j < lim; j++) {
            int s0 = __shfl_sync(0xffffffffu, xv, j);
            float4 v0 = *(const float4*)(sXT + s0 * Dd + lane * 4);
            acc.x += v0.x; acc.y += v0.y; acc.z += v0.z; acc.w += v0.w;
        }
    }
    acc.x += a1.x + a2.x + a3.x;
    acc.y += a1.y + a2.y + a3.y;
    acc.z += a1.z + a2.z + a3.z;
    acc.w += a1.w + a2.w + a3.w;
    return acc;
}

// virtual x' gather: smem vocab row + flag-predicated anchor scaling (sparse patch)
static __device__ __forceinline__ float4 gather_xm(const float* __restrict__ sXT,
                                                   const int* __restrict__ x_idx,
                                                   int n, int lane, float4 acc,
                                                   float4 av, int m) {
    int beg = g_rowptr[n], end = g_rowptr[n + 1];
    for (int b0 = beg; b0 < end; b0 += 32) {
        int lim = end - b0; if (lim > 32) lim = 32;
        int pk = 0;
        if (lane < lim) {
            int s = g_col[b0 + lane];
            pk = x_idx[s] | ((int)g_flag[m * Nn + s] << 8);
        }
        for (int j = 0; j < lim; j++) {
            int p = __shfl_sync(0xffffffffu, pk, j);
            float4 v = *(const float4*)(sXT + (p & 255) * Dd + lane * 4);
            if (p >> 8) {
                v.x = fmaf(v.x, av.x, v.x);
                v.y = fmaf(v.y, av.y, v.y);
                v.z = fmaf(v.z, av.z, v.z);
                v.w = fmaf(v.w, av.w, v.w);
            }
            acc.x += v.x; acc.y += v.y; acc.z += v.z; acc.w += v.w;
        }
    }
    return acc;
}

// ---------------- small kernels ----------------
__global__ void k_reset() {
    int i = blockIdx.x * blockDim.x + threadIdx.x;
    if (i < Mm * Nn) { g_flag[i] = 0; g_amark[i] = 0; }
    if (i < Nn) { g_deg[i] = 0; g_cursor[i] = 0; g_pm[i] = 0; }
    if (i < Mm * NGg * Dd) g_hg[i] = 0.f;
    if (i < NGg) g_counts[i] = 0;
    if (i == 0) g_naff = 0;
}

__global__ void k_hist(const int* __restrict__ edst, const int* __restrict__ batch) {
    int e = blockIdx.x * blockDim.x + threadIdx.x;
    if (e < Ee) atomicAdd(&g_deg[edst[e]], 1);
    if (e < Nn) atomicAdd(&g_counts[batch[e]], 1);
}

// Y1[v] = x_table[v] @ Wg1  (one block per vocab row)
__global__ __launch_bounds__(128) void k_prep(const float* __restrict__ x_table,
                                              const float* __restrict__ Wg) {
    __shared__ float sx[Dd];
    int v = blockIdx.x, c = threadIdx.x;
    sx[c] = x_table[v * Dd + c];
    __syncthreads();
    float y = 0.f;
#pragma unroll 8
    for (int k = 0; k < Dd; k++) y = fmaf(sx[k], Wg[k * Dd + c], y);
    g_Y1[v * Dd + c] = y;
}

// ---------------- multi-block exclusive scan of g_deg -> g_rowptr ----------------
__global__ __launch_bounds__(256) void k_scanA() {
    __shared__ int ss[256];
    int b = blockIdx.x, t = threadIdx.x;
    int i = b * 256 + t;
    int v = (i < Nn) ? g_deg[i] : 0;
    ss[t] = v;
    __syncthreads();
    for (int off = 1; off < 256; off <<= 1) {
        int x = (t >= off) ? ss[t - off] : 0;
        __syncthreads();
        ss[t] += x;
        __syncthreads();
    }
    if (i < Nn) g_rowptr[i] = ss[t] - v;
    if (t == 255) g_bsum[b] = ss[255];
}

__global__ __launch_bounds__(256) void k_scanB() {
    __shared__ int ss[256];
    int t = threadIdx.x;
    int v = (t < SCAN_NB) ? g_bsum[t] : 0;
    ss[t] = v;
    __syncthreads();
    for (int off = 1; off < 256; off <<= 1) {
        int x = (t >= off) ? ss[t - off] : 0;
        __syncthreads();
        ss[t] += x;
        __syncthreads();
    }
    if (t < SCAN_NB) g_bsum[t] = ss[t] - v;
    if (t == 255) g_rowptr[Nn] = ss[255];
}

__global__ __launch_bounds__(256) void k_scanC() {
    int b = blockIdx.x;
    int i = b * 256 + threadIdx.x;
    if (i < Nn) g_rowptr[i] += g_bsum[b];
}

__global__ void k_fill(const int* __restrict__ esrc, const int* __restrict__ edst) {
    int e = blockIdx.x * blockDim.x + threadIdx.x;
    if (e >= Ee) return;
    int d = edst[e];
    int p = atomicAdd(&g_cursor[d], 1);
    g_col[g_rowptr[d] + p] = esrc[e];
}

// ---------------- fp32 fused gather(+GEMM) ----------------
// insel: 0 = Y1 smem table (pass1 L1, NO GEMM, write g_hAs)
//        1 = virtual x' (sparse patch, GEMM, write overlay g_hA[row])
//        2 = g_hAs (pass1 L2, GEMM + pred epilogue)
#define SM_FUSED_XT ((64 * 129 + 64 + 32 * 128) * 4)
#define SM_FUSED_H  ((64 * 129 + 64 + 16 * 128) * 4)
__global__ __launch_bounds__(256) void k_fused(
    int insel, int mode,
    const float* __restrict__ W, const float* __restrict__ bias,
    const float* __restrict__ Wd, const float* __restrict__ bd,
    const float* __restrict__ anchor_table,
    const int* __restrict__ x_idx, const float* __restrict__ x_table,
    int nrows, int sparse)
{
    extern __shared__ float sm[];
    float* sIn = sm;
    int*   sRow = (int*)(sIn + 64 * 129);
    float* sU = (float*)(sRow + 64);
    int t = threadIdx.x, lane = t & 31, wid = t >> 5;
    int rg = t >> 4, cg = t & 15;
    int total = sparse ? g_naff : nrows;

    for (int tile = blockIdx.x; tile * 64 < total; tile += gridDim.x) {
        if (t < 64) {
            int idx = tile * 64 + t;
            sRow[t] = (idx < total) ? (sparse ? g_alist[idx] : idx) : -1;
        }
        if (insel < 2) {
            const float4* src4 = (insel == 0) ? (const float4*)g_Y1
                                              : (const float4*)x_table;
            float4* s4 = (float4*)sU;
            for (int i = t; i < 1024; i += 256) s4[i] = src4[i];
        }
        __syncthreads();

        for (int rr = wid; rr < 64; rr += 8) {
            int grow = sRow[rr];
            float4 acc = make_float4(0.f, 0.f, 0.f, 0.f);
            if (grow >= 0) {
                if (insel == 0) {
                    int xi = x_idx[grow];
                    acc = *(const float4*)(sU + xi * Dd + lane * 4);
                    acc = gather_tx(sU, x_idx, grow, lane, acc);
                } else if (insel == 2) {
                    acc = *(const float4*)(g_hAs + (size_t)grow * Dd + lane * 4);
                    acc = gather_row(g_hAs, grow, lane, acc);
                } else {
                    int m = grow / Nn, n = grow - m * Nn;
                    float4 av = *(const float4*)(anchor_table + Dd + lane * 4);
                    int xi = x_idx[n];
                    acc = *(const float4*)(sU + xi * Dd + lane * 4);
                    if (g_flag[grow]) {
                        acc.x = fmaf(acc.x, av.x, acc.x);
                        acc.y = fmaf(acc.y, av.y, acc.y);
                        acc.z = fmaf(acc.z, av.z, acc.z);
                        acc.w = fmaf(acc.w, av.w, acc.w);
                    }
                    acc = gather_xm(sU, x_idx, n, lane, acc, av, m);
                }
            }
            float* d = &sIn[rr * 129 + lane * 4];
            d[0] = acc.x; d[1] = acc.y; d[2] = acc.z; d[3] = acc.w;
        }
        __syncthreads();

        if (mode == 0) {
            // L1: staged values ARE the result (Y1 table) — single shared write
            for (int idx = t; idx < 2048; idx += 256) {
                int rr = idx >> 5, q = idx & 31;
                int grow = sRow[rr];
                if (grow < 0) continue;
                const float* sp = sIn + rr * 129 + q * 4;
                float4 b4 = *(const float4*)(bias + q * 4);
                float4 v;
                v.x = fmaxf(sp[0] + b4.x, 0.f);
                v.y = fmaxf(sp[1] + b4.y, 0.f);
                v.z = fmaxf(sp[2] + b4.z, 0.f);
                v.w = fmaxf(sp[3] + b4.w, 0.f);
                *(float4*)(g_hAs + (size_t)grow * Dd + q * 4) = v;
            }
            __syncthreads();
            continue;
        }

        float acc[4][8];
#pragma unroll
        for (int r = 0; r < 4; r++)
#pragma unroll
            for (int j = 0; j < 8; j++) acc[r][j] = 0.f;

        for (int kc = 0; kc < 8; kc++) {
            const float4* Ws = (const float4*)(W + kc * 16 * 128);
            ((float4*)sU)[t] = Ws[t];
            ((float4*)sU)[t + 256] = Ws[t + 256];
            __syncthreads();
#pragma unroll
            for (int kk = 0; kk < 16; kk++) {
                float a[4], w[8];
#pragma unroll
                for (int r = 0; r < 4; r++) a[r] = sIn[(rg + 16 * r) * 129 + kc * 16 + kk];
#pragma unroll
                for (int j = 0; j < 8; j++) w[j] = sU[kk * 128 + cg + 16 * j];
#pragma unroll
                for (int r = 0; r < 4; r++)
#pragma unroll
                    for (int j = 0; j < 8; j++) acc[r][j] = fmaf(a[r], w[j], acc[r][j]);
            }
            __syncthreads();
        }

        if (mode == 1) {
#pragma unroll
            for (int r = 0; r < 4; r++) {
                int grow = sRow[rg + 16 * r];
                float p = 0.f;
#pragma unroll
                for (int j = 0; j < 8; j++) {
                    float v = fmaxf(acc[r][j] + bias[cg + 16 * j], 0.f);
                    p = fmaf(v, Wd[cg + 16 * j], p);
                }
#pragma unroll
                for (int o = 8; o > 0; o >>= 1) p += __shfl_xor_sync(0xffffffffu, p, o);
                if (cg == 0 && grow >= 0) g_pred[grow] = p + bd[0];
            }
        } else {
#pragma unroll
            for (int r = 0; r < 4; r++) {
                int rr = rg + 16 * r; int grow = sRow[rr];
                if (grow < 0) continue;
#pragma unroll
                for (int j = 0; j < 8; j++) {
                    float v = fmaxf(acc[r][j] + bias[cg + 16 * j], 0.f);
                    g_hA[(size_t)grow * Dd + cg + 16 * j] = v;   // overlay
                }
            }
        }
        __syncthreads();
    }
}

// ---------------- tf32 mma.sync GEMM (256 thr, 2 blocks/SM) ----------------
#define SW_STR 136
#define SI_STR 132
#define SMEM_MMA ((128 * SW_STR + 64 * SI_STR) * 4 + 64 * 4)

static __device__ __forceinline__ void mma_tf32(float* c, const uint32_t* a, const uint32_t* b) {
    asm volatile(
        "mma.sync.aligned.m16n8k8.row.col.f32.tf32.tf32.f32 "
        "{%0,%1,%2,%3}, {%4,%5,%6,%7}, {%8,%9}, {%0,%1,%2,%3};"
        : "+f"(c[0]), "+f"(c[1]), "+f"(c[2]), "+f"(c[3])
        : "r"(a[0]), "r"(a[1]), "r"(a[2]), "r"(a[3]), "r"(b[0]), "r"(b[1]));
}

// paired=1: tile = 32 nodes x 2 m, shared gather + sparse overlay corrections
__global__ __launch_bounds__(256) void k_mma(
    int paired, int pool,
    const float* __restrict__ W, const float* __restrict__ bias,
    const int* __restrict__ batch, int nrows)
{
    extern __shared__ float sm[];
    float* sW = sm;
    float* sIn = sm + 128 * SW_STR;
    int* sRow = (int*)(sIn + 64 * SI_STR);
    int t = threadIdx.x, lane = t & 31, wid = t >> 5;
    int gid = lane >> 2, tig = lane & 3;
    int wr = wid >> 2, wc = wid & 3;

    for (int idx = t; idx < 16384; idx += 256) {
        int k = idx >> 7, c = idx & 127;
        sW[k * SW_STR + c] = __uint_as_float(f2tf32(W[idx]));
    }

    int ntile = paired ? ((nrows + 31) >> 5) : ((nrows + 63) >> 6);
    for (int tile = blockIdx.x; tile < ntile; tile += gridDim.x) {
        if (t < 64) {
            if (paired) {
                int node = tile * 32 + (t >> 1);
                sRow[t] = (node < Nn) ? ((t & 1) * Nn + node) : -1;
            } else {
                int idx = tile * 64 + t;
                sRow[t] = (idx < nrows) ? idx : -1;
            }
        }
        __syncthreads();

        if (paired) {
            for (int ni = wid; ni < 32; ni += 8) {
                int n = tile * 32 + ni;
                float4 acc = make_float4(0.f, 0.f, 0.f, 0.f);
                float4 a1 = make_float4(0.f, 0.f, 0.f, 0.f);
                float4 a2 = make_float4(0.f, 0.f, 0.f, 0.f);
                float4 a3 = make_float4(0.f, 0.f, 0.f, 0.f);
                float4 c0 = make_float4(0.f, 0.f, 0.f, 0.f);
                float4 c1 = make_float4(0.f, 0.f, 0.f, 0.f);
                float4 r0 = acc, r1 = acc;
                if (n < Nn) {
                    int beg = g_rowptr[n], end = g_rowptr[n + 1];
                    for (int b0 = beg; b0 < end; b0 += 32) {
                        int lim = end - b0; if (lim > 32) lim = 32;
                        int cidx = 0, pmk = 0;
                        if (lane < lim) {
                            cidx = g_col[b0 + lane];
                            pmk = g_pm[cidx];
                        }
                        int j = 0;
                        for (; j + 4 <= lim; j += 4) {
                            int s0 = __shfl_sync(0xffffffffu, cidx, j);
                            int s1 = __shfl_sync(0xffffffffu, cidx, j + 1);
                            int s2 = __shfl_sync(0xffffffffu, cidx, j + 2);
                            int s3 = __shfl_sync(0xffffffffu, cidx, j + 3);
                            float4 v0 = *(const float4*)(g_hAs + (size_t)s0 * Dd + lane * 4);
                            float4 v1 = *(const float4*)(g_hAs + (size_t)s1 * Dd + lane * 4);
                            float4 v2 = *(const float4*)(g_hAs + (size_t)s2 * Dd + lane * 4);
                            float4 v3 = *(const float4*)(g_hAs + (size_t)s3 * Dd + lane * 4);
                            acc.x += v0.x; acc.y += v0.y; acc.z += v0.z; acc.w += v0.w;
                            a1.x += v1.x; a1.y += v1.y; a1.z += v1.z; a1.w += v1.w;
                            a2.x += v2.x; a2.y += v2.y; a2.z += v2.z; a2.w += v2.w;
                            a3.x += v3.x; a3.y += v3.y; a3.z += v3.z; a3.w += v3.w;
                        }
                        for (; j < lim; j++) {
                            int s0 = __shfl_sync(0xffffffffu, cidx, j);
                            float4 v0 = *(const float4*)(g_hAs + (size_t)s0 * Dd + lane * 4);
                            acc.x += v0.x; acc.y += v0.y; acc.z += v0.z; acc.w += v0.w;
                        }
                        // rare corrections for patched neighbors
                        unsigned mb = __ballot_sync(0xffffffffu, pmk != 0);
                        while (mb) {
                            int jj = __ffs(mb) - 1; mb &= mb - 1;
                            int s = __shfl_sync(0xffffffffu, cidx, jj);
                            int pm = __shfl_sync(0xffffffffu, pmk, jj);
                            float4 sh = *(const float4*)(g_hAs + (size_t)s * Dd + lane * 4);
                            if (pm & 1) {
                                float4 ov = *(const float4*)(g_hA + (size_t)s * Dd + lane * 4);
                                c0.x += ov.x - sh.x; c0.y += ov.y - sh.y;
                                c0.z += ov.z - sh.z; c0.w += ov.w - sh.w;
                            }
                            if (pm & 2) {
                                float4 ov = *(const float4*)(g_hA + (size_t)(s + Nn) * Dd + lane * 4);
                                c1.x += ov.x - sh.x; c1.y += ov.y - sh.y;
                                c1.z += ov.z - sh.z; c1.w += ov.w - sh.w;
                            }
                        }
                    }
                    acc.x += a1.x + a2.x + a3.x;
                    acc.y += a1.y + a2.y + a3.y;
                    acc.z += a1.z + a2.z + a3.z;
                    acc.w += a1.w + a2.w + a3.w;
                    // self rows
                    float4 sh = *(const float4*)(g_hAs + (size_t)n * Dd + lane * 4);
                    int pmn = g_pm[n];
                    float4 s0 = sh, s1 = sh;
                    if (pmn & 1) s0 = *(const float4*)(g_hA + (size_t)n * Dd + lane * 4);
                    if (pmn & 2) s1 = *(const float4*)(g_hA + (size_t)(n + Nn) * Dd + lane * 4);
                    r0.x = acc.x + c0.x + s0.x; r0.y = acc.y + c0.y + s0.y;
                    r0.z = acc.z + c0.z + s0.z; r0.w = acc.w + c0.w + s0.w;
                    r1.x = acc.x + c1.x + s1.x; r1.y = acc.y + c1.y + s1.y;
                    r1.z = acc.z + c1.z + s1.z; r1.w = acc.w + c1.w + s1.w;
                }
                float* d0 = &sIn[(2 * ni) * SI_STR + lane * 4];
                float* d1 = &sIn[(2 * ni + 1) * SI_STR + lane * 4];
                d0[0] = __uint_as_float(f2tf32(r0.x));
                d0[1] = __uint_as_float(f2tf32(r0.y));
                d0[2] = __uint_as_float(f2tf32(r0.z));
                d0[3] = __uint_as_float(f2tf32(r0.w));
                d1[0] = __uint_as_float(f2tf32(r1.x));
                d1[1] = __uint_as_float(f2tf32(r1.y));
                d1[2] = __uint_as_float(f2tf32(r1.z));
                d1[3] = __uint_as_float(f2tf32(r1.w));
            }
        } else {
            for (int rr = wid; rr < 64; rr += 8) {
                int grow = sRow[rr];
                float4 acc = make_float4(0.f, 0.f, 0.f, 0.f);
                if (grow >= 0) {
                    int m = grow / Nn, n = grow - m * Nn;
                    const float* base = g_hB + (size_t)m * Nn * Dd;
                    acc = *(const float4*)(base + (size_t)n * Dd + lane * 4);
                }
                float* d = &sIn[rr * SI_STR + lane * 4];
                d[0] = __uint_as_float(f2tf32(acc.x));
                d[1] = __uint_as_float(f2tf32(acc.y));
                d[2] = __uint_as_float(f2tf32(acc.z));
                d[3] = __uint_as_float(f2tf32(acc.w));
            }
        }
        __syncthreads();

        float c_[2][4][4];
#pragma unroll
        for (int mt = 0; mt < 2; mt++)
#pragma unroll
            for (int nt = 0; nt < 4; nt++)
#pragma unroll
                for (int q = 0; q < 4; q++) c_[mt][nt][q] = 0.f;

#pragma unroll 4
        for (int ks = 0; ks < 16; ks++) {
            int k0 = ks * 8;
            uint32_t a[2][4], b[4][2];
#pragma unroll
            for (int mt = 0; mt < 2; mt++) {
                const float* Ap = sIn + (wr * 32 + mt * 16 + gid) * SI_STR + k0 + tig;
                a[mt][0] = __float_as_uint(Ap[0]);
                a[mt][1] = __float_as_uint(Ap[8 * SI_STR]);
                a[mt][2] = __float_as_uint(Ap[4]);
                a[mt][3] = __float_as_uint(Ap[8 * SI_STR + 4]);
            }
#pragma unroll
            for (int nt = 0; nt < 4; nt++) {
                const float* Bp = sW + (k0 + tig) * SW_STR + wc * 32 + nt * 8 + gid;
                b[nt][0] = __float_as_uint(Bp[0]);
                b[nt][1] = __float_as_uint(Bp[4 * SW_STR]);
            }
#pragma unroll
            for (int mt = 0; mt < 2; mt++)
#pragma unroll
                for (int nt = 0; nt < 4; nt++)
                    mma_tf32(c_[mt][nt], a[mt], b[nt]);
        }
        __syncthreads();

#pragma unroll
        for (int mt = 0; mt < 2; mt++) {
#pragma unroll
            for (int nt = 0; nt < 4; nt++) {
                int col = wc * 32 + nt * 8 + tig * 2;
                int row = wr * 32 + mt * 16 + gid;
                float b0 = bias[col], b1 = bias[col + 1];
                sIn[row * SI_STR + col]           = fmaxf(c_[mt][nt][0] + b0, 0.f);
                sIn[row * SI_STR + col + 1]       = fmaxf(c_[mt][nt][1] + b1, 0.f);
                sIn[(row + 8) * SI_STR + col]     = fmaxf(c_[mt][nt][2] + b0, 0.f);
                sIn[(row + 8) * SI_STR + col + 1] = fmaxf(c_[mt][nt][3] + b1, 0.f);
            }
        }
        __syncthreads();

        if (pool) {
            int col = t & 127, half = t >> 7;
            float s = 0.f; int cur = -1;
            for (int rr = half * 32; rr < half * 32 + 32; rr++) {
                int grow = sRow[rr]; if (grow < 0) continue;
                int m = grow / Nn;
                int key = m * NGg + batch[grow - m * Nn];
                if (key != cur) {
                    if (cur >= 0) atomicAdd(&g_hg[(size_t)cur * Dd + col], s);
                    cur = key; s = 0.f;
                }
                s += sIn[rr * SI_STR + col];
            }
            if (cur >= 0) atomicAdd(&g_hg[(size_t)cur * Dd + col], s);
        } else {
            for (int idx = t; idx < 2048; idx += 256) {
                int rr = idx >> 5, q = idx & 31;
                int grow = sRow[rr];
                if (grow < 0) continue;
                *(float4*)(g_hB + (size_t)grow * Dd + q * 4) =
                    *(float4*)(sIn + rr * SI_STR + q * 4);
            }
        }
        __syncthreads();
    }
}

// ---------------- fused per-graph sampling ----------------
static __device__ __forceinline__ float score_fn(int n, int m, float mx, float ssum,
                                                 unsigned fk0, unsigned fk1) {
    float e = expf(g_pred[n] - mx);
    float p = e / ssum;
    float lp = logf(p + 1e-15f);
    unsigned x0 = 0u, x1 = (unsigned)(m * Nn + n);
    tf2x32(fk0, fk1, x0, x1);
    float u = __uint_as_float((x1 >> 9) | 0x3F800000u) - 1.0f;
    u = fmaxf(u, 0.0f);
    float gum = -logf(-logf(u + 1e-12f) + 1e-12f);
    return lp + gum;
}

__global__ void k_sample(const int* __restrict__ batch, unsigned fk0, unsigned fk1) {
    __shared__ float fb[8];
    __shared__ int ib[8];
    __shared__ int sSE[2];
    __shared__ float sMx, sSum, sBest;
    int g = blockIdx.x, t = threadIdx.x, lane = t & 31, wid = t >> 5;
    if (t < 2) {
        int tgt = g + t;
        int lo = 0, hi = Nn;
        while (lo < hi) { int mid = (lo + hi) >> 1; if (batch[mid] < tgt) lo = mid + 1; else hi = mid; }
        sSE[t] = lo;
    }
    __syncthreads();
    int s0 = sSE[0], s1 = sSE[1];

    float mx = -3.4e38f;
    for (int n = s0 + t; n < s1; n += 256) mx = fmaxf(mx, g_pred[n]);
#pragma unroll
    for (int o = 16; o > 0; o >>= 1) mx = fmaxf(mx, __shfl_xor_sync(0xffffffffu, mx, o));
    if (lane == 0) fb[wid] = mx;
    __syncthreads();
    if (t == 0) { float x = fb[0]; for (int i = 1; i < 8; i++) x = fmaxf(x, fb[i]); sMx = x; }
    __syncthreads();
    float gmx = sMx;

    float sm = 0.f;
    for (int n = s0 + t; n < s1; n += 256) sm += expf(g_pred[n] - gmx);
#pragma unroll
    for (int o = 16; o > 0; o >>= 1) sm += __shfl_xor_sync(0xffffffffu, sm, o);
    if (lane == 0) fb[wid] = sm;
    __syncthreads();
    if (t == 0) { float x = 0.f; for (int i = 0; i < 8; i++) x += fb[i]; sSum = x; }
    __syncthreads();
    float gsum = sSum;

    for (int m = 0; m < Mm; m++) {
        float best = -3.4e38f;
        for (int n = s0 + t; n < s1; n += 256)
            best = fmaxf(best, score_fn(n, m, gmx, gsum, fk0, fk1));
#pragma unroll
        for (int o = 16; o > 0; o >>= 1) best = fmaxf(best, __shfl_xor_sync(0xffffffffu, best, o));
        if (lane == 0) fb[wid] = best;
        __syncthreads();
        if (t == 0) { float x = fb[0]; for (int i = 1; i < 8; i++) x = fmaxf(x, fb[i]); sBest = x; }
        __syncthreads();
        float gb = sBest;
        __syncthreads();

        int cand = Nn;
        for (int n = s0 + t; n < s1; n += 256)
            if (score_fn(n, m, gmx, gsum, fk0, fk1) >= gb) cand = min(cand, n);
#pragma unroll
        for (int o = 16; o > 0; o >>= 1) cand = min(cand, __shfl_xor_sync(0xffffffffu, cand, o));
        if (lane == 0) ib[wid] = cand;
        __syncthreads();
        if (t == 0) {
            int x = ib[0]; for (int i = 1; i < 8; i++) x = min(x, ib[i]);
            if (x < Nn) {
                g_flag[m * Nn + x] = 1;
                atomicOr(&g_pm[x], 1 << m);
                if (atomicExch(&g_amark[m * Nn + x], 1) == 0) {
                    int p = atomicAdd(&g_naff, 1);
                    g_alist[p] = m * Nn + x;
                }
            }
        }
        __syncthreads();
    }
}

// single-pass mark: rows whose L1 aggregation changes per m
__global__ void k_mark(const int* __restrict__ esrc, const int* __restrict__ edst) {
    int e = blockIdx.x * blockDim.x + threadIdx.x;
    if (e >= Ee) return;
    int s = esrc[e];
    unsigned char f0 = g_flag[s];
    unsigned char f1 = g_flag[Nn + s];
    if (!(f0 | f1)) return;
    int d = edst[e];
    if (f0 && atomicExch(&g_amark[d], 1) == 0) {
        int p = atomicAdd(&g_naff, 1);
        g_alist[p] = d;
        atomicOr(&g_pm[d], 1);
    }
    if (f1 && atomicExch(&g_amark[Nn + d], 1) == 0) {
        int p = atomicAdd(&g_naff, 1);
        g_alist[p] = Nn + d;
        atomicOr(&g_pm[d], 2);
    }
}

__global__ void k_final(const float* __restrict__ Wp, const float* __restrict__ bp,
                        float* __restrict__ out) {
    __shared__ float red[128];
    int g = blockIdx.x, t = threadIdx.x;
    int c = g_counts[g]; if (c < 1) c = 1;
    float inv = 1.0f / (float)c;
    float hsum = (g_hg[(size_t)g * Dd + t] + g_hg[((size_t)NGg + g) * Dd + t]) * inv;
    for (int tt = 0; tt < 10; tt++) {
        red[t] = hsum * Wp[t * 10 + tt];
        __syncthreads();
        for (int off = 64; off > 0; off >>= 1) {
            if (t < off) red[t] += red[t + off];
            __syncthreads();
        }
        if (t == 0) out[g * 10 + tt] = red[0] * 0.5f + bp[tt];
        __syncthreads();
    }
}

// ---------------- launch ----------------
static inline int cdiv(int a, int b) { return (a + b - 1) / b; }

extern "C" void kernel_launch(void* const* d_in, const int* in_sizes, int n_in,
                              void* d_out, int out_size) {
    const int*   x_idx        = (const int*)d_in[0];
    const int*   esrc         = (const int*)d_in[1];
    const int*   edst         = (const int*)d_in[2];
    const int*   batch        = (const int*)d_in[3];
    const float* x_table      = (const float*)d_in[4];
    const float* anchor_table = (const float*)d_in[5];
    const float* Wg           = (const float*)d_in[6];
    const float* bg           = (const float*)d_in[7];
    const float* Wn           = (const float*)d_in[8];
    const float* bn           = (const float*)d_in[9];
    const float* Wd           = (const float*)d_in[10];
    const float* bd           = (const float*)d_in[11];
    const float* Wp           = (const float*)d_in[12];
    const float* bp           = (const float*)d_in[13];
    float* out = (float*)d_out;

    unsigned fk0 = 0u, fk1 = 1u;
    tf2x32(0u, 1u, fk0, fk1);

    cudaFuncSetAttribute(k_mma, cudaFuncAttributeMaxDynamicSharedMemorySize, SMEM_MMA);
    cudaFuncSetAttribute(k_fused, cudaFuncAttributeMaxDynamicSharedMemorySize, SM_FUSED_XT);

    // setup
    k_reset<<<cdiv(Mm * Nn, 256), 256>>>();
    k_hist<<<cdiv(Ee, 256), 256>>>(edst, batch);
    k_prep<<<32, 128>>>(x_table, Wg);
    k_scanA<<<SCAN_NB, 256>>>();
    k_scanB<<<1, 256>>>();
    k_scanC<<<SCAN_NB, 256>>>();
    k_fill<<<cdiv(Ee, 256), 256>>>(esrc, edst);

    // pass1 L1: Y1 smem-table gather, NO GEMM -> shared g_hAs
    k_fused<<<cdiv(Nn, 64), 256, SM_FUSED_XT>>>(0, 0, Wg, bg, nullptr, nullptr,
                                                nullptr, x_idx, x_table, Nn, 0);
    // pass1 L2: fp32 gather+GEMM + fused pred epilogue (reads g_hAs)
    k_fused<<<cdiv(Nn, 64), 256, SM_FUSED_H>>>(2, 1, Wg + Dd * Dd, bg + Dd, Wd, bd,
                                               nullptr, x_idx, x_table, Nn, 0);

    // anchor sampling + single-pass affected-row marking (sets g_pm)
    k_sample<<<NGg, 256>>>(batch, fk0, fk1);
    k_mark<<<cdiv(Ee, 256), 256>>>(esrc, edst);

    // pass2 L1: sparse patch -> overlay g_hA rows (fp32 exact)
    k_fused<<<148, 256, SM_FUSED_XT>>>(1, 2, Wg, bg, nullptr, nullptr,
                                       anchor_table, x_idx, x_table, 0, 1);

    // pass2 L2 (tf32 mma, PAIRED): shared gather + overlay corrections -> hB
    k_mma<<<296, 256, SMEM_MMA>>>(1, 0, Wg + Dd * Dd, bg + Dd, batch, Nn);
    // node MLP + pooled epilogue (tf32): hB -> hg
    k_mma<<<296, 256, SMEM_MMA>>>(0, 1, Wn, bn, batch, Mm * Nn);

    // final projection + mean over m
    k_final<<<NGg, 128>>>(Wp, bp, out);
}